// round 7
// baseline (speedup 1.0000x reference)
#include <cuda_runtime.h>
#include <cstdint>
#include <math.h>

#define Bsz   1024
#define Az    5
#define Nz    16384
#define Dz    512
#define TOPK  50
#define NSTEP 5
#define MT    13   // max padded 128-row tiles: sum ceil(cnt/128) <= 12, +1 margin

// ---- scratch (device globals, no allocations) ----
__device__ float g_sims[(size_t)Bsz * Nz];            // 64 MB
__device__ float g_kn[(size_t)Az * Nz * Dz];          // 168 MB normalized keys
__device__ float g_qn[Bsz * Dz];                      // normalized query (emb or cur)
__device__ float g_cur[Bsz * Dz];                     // raw cur (MLP input)
__device__ float g_kdenom[Az * Nz];
__device__ float g_qdenom[Bsz];
__device__ int   g_row_map[NSTEP][MT * 128];
__device__ int   g_tile_action[NSTEP][MT];

__device__ __forceinline__ float warp_sum(float v) {
#pragma unroll
    for (int o = 16; o; o >>= 1) v += __shfl_xor_sync(0xffffffffu, v, o);
    return v;
}

// Cephes/Eigen-style expf (fma Horner, Cody-Waite) to track XLA's CPU exp
__device__ __forceinline__ float ref_exp(float x) {
    float m = floorf(fmaf(x, 1.44269504088896341f, 0.5f));
    float r = fmaf(m, -0.693359375f, x);
    r = fmaf(m, 2.12194440e-4f, r);
    float r2 = r * r;
    float p = 1.9875691500E-4f;
    p = fmaf(p, r, 1.3981999507E-3f);
    p = fmaf(p, r, 8.3334519073E-3f);
    p = fmaf(p, r, 4.1665795894E-2f);
    p = fmaf(p, r, 1.6666665459E-1f);
    p = fmaf(p, r, 5.0000001201E-1f);
    float y = fmaf(p, r2, r) + 1.0f;
    return ldexpf(y, (int)m);
}

// ---------------- row denominators: ||x|| + eps, 8-accumulator vector-lane order ----------------
__global__ void row_denom_kernel(const float* __restrict__ X, int which, int nrows) {
    int r = blockIdx.x * blockDim.x + threadIdx.x;
    if (r >= nrows) return;
    const float4* p = (const float4*)(X + (size_t)r * Dz);
    float a[8];
#pragma unroll
    for (int j = 0; j < 8; j++) a[j] = 0.f;
    for (int i = 0; i < Dz / 8; i++) {
        float4 v0 = p[2 * i];
        float4 v1 = p[2 * i + 1];
        a[0] = fmaf(v0.x, v0.x, a[0]); a[1] = fmaf(v0.y, v0.y, a[1]);
        a[2] = fmaf(v0.z, v0.z, a[2]); a[3] = fmaf(v0.w, v0.w, a[3]);
        a[4] = fmaf(v1.x, v1.x, a[4]); a[5] = fmaf(v1.y, v1.y, a[5]);
        a[6] = fmaf(v1.z, v1.z, a[6]); a[7] = fmaf(v1.w, v1.w, a[7]);
    }
    float e0 = a[0] + a[4], e1 = a[1] + a[5], e2 = a[2] + a[6], e3 = a[3] + a[7];
    float f0 = e0 + e2, f1 = e1 + e3;
    float s = f0 + f1;
    float d = __fsqrt_rn(s) + 1e-8f;
    if (which) g_qdenom[r] = d; else g_kdenom[r] = d;
}

// ---------------- elementwise normalize with IEEE division ----------------
__global__ void normalize_kernel(const float* __restrict__ X, int which, int n4) {
    float* Y = which ? g_qn : g_kn;
    const float* D = which ? g_qdenom : g_kdenom;
    for (int i = blockIdx.x * blockDim.x + threadIdx.x; i < n4; i += gridDim.x * blockDim.x) {
        float4 v = ((const float4*)X)[i];
        float d = D[i >> 7];   // Dz/4 = 128 float4 per row
        float4 o;
        o.x = __fdiv_rn(v.x, d); o.y = __fdiv_rn(v.y, d);
        o.z = __fdiv_rn(v.z, d); o.w = __fdiv_rn(v.w, d);
        ((float4*)Y)[i] = o;
    }
}

// ---------------- group batches by selected action, per step ----------------
__global__ void group_kernel(const int* __restrict__ actions) {
    __shared__ int cnt[Az], cur[Az];
    int tid = threadIdx.x;
    for (int t = 0; t < NSTEP; t++) {
        if (tid < Az) cnt[tid] = 0;
        __syncthreads();
        for (int b = tid; b < Bsz; b += blockDim.x)
            atomicAdd(&cnt[actions[b * NSTEP + t]], 1);
        __syncthreads();
        if (tid == 0) {
            int off = 0;
            for (int a = 0; a < Az; a++) {
                cur[a] = off;
                off += ((cnt[a] + 127) >> 7) << 7;
            }
        }
        __syncthreads();
        for (int i = tid; i < MT * 128; i += blockDim.x) g_row_map[t][i] = -1;
        __syncthreads();
        for (int b = tid; b < Bsz; b += blockDim.x) {
            int a = actions[b * NSTEP + t];
            int p = atomicAdd(&cur[a], 1);
            g_row_map[t][p] = b;
        }
        if (tid < MT) {
            int mt = tid, act = -1, off = 0;
            for (int a = 0; a < Az; a++) {
                int len = ((cnt[a] + 127) >> 7) << 7;
                if (mt * 128 >= off && mt * 128 < off + len) act = a;
                off += len;
            }
            g_tile_action[t][mt] = act;
        }
        __syncthreads();
    }
}

// ---------------- grouped fp32 GEMM on pre-normalized tensors ----------------
// sims[b][n] = sum_d qn[b][d]*kn[a][n][d], strict d-ascending single-accumulator fma chain
__global__ __launch_bounds__(256, 2) void sims_gemm(int t) {
    int mt = blockIdx.y;
    int act = g_tile_action[t][mt];
    if (act < 0) return;
    int n0 = blockIdx.x * 128;

    __shared__ float As[8][132];
    __shared__ float Bs[8][132];
    __shared__ int   rs[128];

    int tid = threadIdx.x;
    if (tid < 128) rs[tid] = g_row_map[t][mt * 128 + tid];
    __syncthreads();

    int li = tid >> 1;           // 0..127
    int lk = (tid & 1) << 2;     // 0 or 4
    int arow = rs[li];
    const float* ap = g_qn + (size_t)(arow < 0 ? 0 : arow) * Dz + lk;
    const float* bp = g_kn + ((size_t)act * Nz + n0 + li) * Dz + lk;

    int tx = tid & 15, ty = tid >> 4;

    float acc[8][8];
#pragma unroll
    for (int i = 0; i < 8; i++)
#pragma unroll
        for (int j = 0; j < 8; j++) acc[i][j] = 0.f;

    for (int k0 = 0; k0 < Dz; k0 += 8) {
        float4 av = (arow >= 0) ? *(const float4*)(ap + k0) : make_float4(0, 0, 0, 0);
        float4 bv = *(const float4*)(bp + k0);
        As[lk + 0][li] = av.x; As[lk + 1][li] = av.y; As[lk + 2][li] = av.z; As[lk + 3][li] = av.w;
        Bs[lk + 0][li] = bv.x; Bs[lk + 1][li] = bv.y; Bs[lk + 2][li] = bv.z; Bs[lk + 3][li] = bv.w;
        __syncthreads();
#pragma unroll
        for (int kk = 0; kk < 8; kk++) {
            float a[8], b[8];
            *(float4*)(a)     = *(const float4*)(&As[kk][ty * 4]);
            *(float4*)(a + 4) = *(const float4*)(&As[kk][64 + ty * 4]);
            *(float4*)(b)     = *(const float4*)(&Bs[kk][tx * 4]);
            *(float4*)(b + 4) = *(const float4*)(&Bs[kk][64 + tx * 4]);
#pragma unroll
            for (int i = 0; i < 8; i++)
#pragma unroll
                for (int j = 0; j < 8; j++) acc[i][j] = fmaf(a[i], b[j], acc[i][j]);
        }
        __syncthreads();
    }

#pragma unroll
    for (int i = 0; i < 8; i++) {
        int rl = (i < 4) ? (ty * 4 + i) : (64 + ty * 4 + i - 4);
        int r = rs[rl];
        if (r < 0) continue;
        float* srow = g_sims + (size_t)r * Nz + n0;
#pragma unroll
        for (int j = 0; j < 8; j++) {
            int cl = (j < 4) ? (tx * 4 + j) : (64 + tx * 4 + j - 4);
            srow[cl] = acc[i][j];
        }
    }
}

// ---------------- exact top-50 (radix select) + reference-ordered softmax + gather ----------------
__global__ __launch_bounds__(256) void topk_kernel(const float* __restrict__ memv,
                                                   const int* __restrict__ actions, int t) {
    __shared__ unsigned int hist[4096];
    __shared__ unsigned int sh_prefix;
    __shared__ int sh_r;
    __shared__ float s_val[TOPK];
    __shared__ int   s_idx[TOPK];
    __shared__ int   s_cgt, s_ctie;
    __shared__ int   s_tie[256];
    __shared__ float s_cur[Dz];
    __shared__ float s_acc8[8];
    __shared__ float sh_denom;

    int b = blockIdx.x;
    int tid = threadIdx.x;
    const float4* srow4 = (const float4*)(g_sims + (size_t)b * Nz);

    const int widths[4] = {12, 8, 8, 4};
    unsigned int prefix = 0;
    int nb = 0;
    int r = TOPK;

#pragma unroll
    for (int p = 0; p < 4; p++) {
        int w = widths[p];
        int bins = 1 << w;
        int shift = 32 - nb - w;
        for (int i = tid; i < bins; i += 256) hist[i] = 0u;
        __syncthreads();
        for (int i4 = tid; i4 < Nz / 4; i4 += 256) {
            float4 v = srow4[i4];
            float xs[4] = {v.x, v.y, v.z, v.w};
#pragma unroll
            for (int c = 0; c < 4; c++) {
                unsigned int u = __float_as_uint(xs[c]);
                u = (u & 0x80000000u) ? ~u : (u | 0x80000000u);
                bool ok = (nb == 0) || ((u >> (32 - nb)) == prefix);
                if (ok) atomicAdd(&hist[(u >> shift) & (unsigned)(bins - 1)], 1u);
            }
        }
        __syncthreads();
        if (tid == 0) {
            int cum = 0, bin = bins - 1;
            for (; bin >= 0; bin--) {
                cum += (int)hist[bin];
                if (cum >= r) break;
            }
            r -= (cum - (int)hist[bin]);
            sh_prefix = (prefix << w) | (unsigned)bin;
            sh_r = r;
        }
        __syncthreads();
        prefix = sh_prefix;
        r = sh_r;
        nb += w;
        __syncthreads();
    }

    unsigned int T = prefix;   // exact 32-bit key of the rank-50 element
    if (tid == 0) { s_cgt = 0; s_ctie = 0; }
    __syncthreads();

    for (int i4 = tid; i4 < Nz / 4; i4 += 256) {
        float4 v = srow4[i4];
        float xs[4] = {v.x, v.y, v.z, v.w};
#pragma unroll
        for (int c = 0; c < 4; c++) {
            unsigned int u = __float_as_uint(xs[c]);
            u = (u & 0x80000000u) ? ~u : (u | 0x80000000u);
            if (u > T) {
                int p2 = atomicAdd(&s_cgt, 1);
                if (p2 < TOPK) { s_val[p2] = xs[c]; s_idx[p2] = i4 * 4 + c; }
            } else if (u == T) {
                int p2 = atomicAdd(&s_ctie, 1);
                if (p2 < 256) s_tie[p2] = i4 * 4 + c;
            }
        }
    }
    __syncthreads();

    if (tid == 0) {
        int cgt = min(s_cgt, TOPK);
        int need = TOPK - cgt;
        float Tf = (T & 0x80000000u) ? __uint_as_float(T ^ 0x80000000u) : __uint_as_float(~T);
        int nt = min(s_ctie, 256);
        for (int s = 0; s < need; s++) {   // ties: lowest index first (lax.top_k)
            int mi = -1, mv = 0x7fffffff;
            for (int q2 = 0; q2 < nt; q2++)
                if (s_tie[q2] < mv) { mv = s_tie[q2]; mi = q2; }
            if (mi >= 0) s_tie[mi] = 0x7fffffff;
            s_val[cgt + s] = Tf;
            s_idx[cgt + s] = mv;
        }
        // sort all 50 exactly like lax.top_k: value desc, index asc
        for (int i = 1; i < TOPK; i++) {
            float v = s_val[i]; int id = s_idx[i];
            int j = i - 1;
            while (j >= 0 && (s_val[j] < v || (s_val[j] == v && s_idx[j] > id))) {
                s_val[j + 1] = s_val[j]; s_idx[j + 1] = s_idx[j];
                j--;
            }
            s_val[j + 1] = v; s_idx[j + 1] = id;
        }
        // softmax in reference order
        float mx = s_val[0];
        float sum = 0.f;
        for (int k2 = 0; k2 < TOPK; k2++) {
            float e = ref_exp(s_val[k2] - mx);
            s_val[k2] = e;
            sum += e;
        }
        for (int k2 = 0; k2 < TOPK; k2++) s_val[k2] = __fdiv_rn(s_val[k2], sum);
    }
    __syncthreads();

    // weighted gather-sum in sorted order, k-ascending fma chain (reference reduction order)
    int a = actions[b * NSTEP + t];
    const float* vb = memv + (size_t)a * Nz * Dz;
    float a0 = 0.f, a1 = 0.f;
    int d0 = tid, d1 = tid + 256;
    for (int k2 = 0; k2 < TOPK; k2++) {
        const float* vr = vb + (size_t)s_idx[k2] * Dz;
        float w2 = s_val[k2];
        a0 = fmaf(w2, vr[d0], a0);
        a1 = fmaf(w2, vr[d1], a1);
    }
    s_cur[d0] = a0;
    s_cur[d1] = a1;
    g_cur[b * Dz + d0] = a0;
    g_cur[b * Dz + d1] = a1;
    __syncthreads();

    // ||cur|| with the same 8-accumulator vector-lane order as row_denom_kernel
    if (tid < 8) {
        float acc = 0.f;
        for (int i = 0; i < Dz / 8; i++) {
            float x = s_cur[8 * i + tid];
            acc = fmaf(x, x, acc);
        }
        s_acc8[tid] = acc;
    }
    __syncthreads();
    if (tid == 0) {
        float e0 = s_acc8[0] + s_acc8[4], e1 = s_acc8[1] + s_acc8[5];
        float e2 = s_acc8[2] + s_acc8[6], e3 = s_acc8[3] + s_acc8[7];
        float f0 = e0 + e2, f1 = e1 + e3;
        sh_denom = __fsqrt_rn(f0 + f1) + 1e-8f;
    }
    __syncthreads();
    float dn = sh_denom;
    g_qn[b * Dz + d0] = __fdiv_rn(a0, dn);
    g_qn[b * Dz + d1] = __fdiv_rn(a1, dn);
}

// ---------------- fused 3-layer MLP (512->256->128->1, elu) ----------------
__global__ __launch_bounds__(256) void mlp_kernel(const float* __restrict__ emb, int use_emb,
                                                  const float* __restrict__ W1, const float* __restrict__ b1,
                                                  const float* __restrict__ W2, const float* __restrict__ b2,
                                                  const float* __restrict__ W3, const float* __restrict__ b3,
                                                  float* __restrict__ out, int off, int stride) {
    __shared__ float Xs[8 * 512];
    __shared__ float H1[8 * 256];
    __shared__ float H2[8 * 128];
    const float* X = use_emb ? emb : g_cur;
    int tid = threadIdx.x;
    int b0 = blockIdx.x * 8;

    for (int i = tid; i < 8 * 512; i += 256) Xs[i] = X[(size_t)b0 * 512 + i];
    __syncthreads();
    {
        int j = tid;  // 0..255
        float acc[8];
#pragma unroll
        for (int bb = 0; bb < 8; bb++) acc[bb] = 0.f;
        for (int d = 0; d < 512; d += 4) {
            float w0 = W1[(d + 0) * 256 + j];
            float w1 = W1[(d + 1) * 256 + j];
            float w2v = W1[(d + 2) * 256 + j];
            float w3v = W1[(d + 3) * 256 + j];
#pragma unroll
            for (int bb = 0; bb < 8; bb++) {
                float4 x = *(const float4*)(&Xs[bb * 512 + d]);
                acc[bb] = fmaf(x.x, w0, acc[bb]);
                acc[bb] = fmaf(x.y, w1, acc[bb]);
                acc[bb] = fmaf(x.z, w2v, acc[bb]);
                acc[bb] = fmaf(x.w, w3v, acc[bb]);
            }
        }
        float bj = b1[j];
#pragma unroll
        for (int bb = 0; bb < 8; bb++) {
            float h = acc[bb] + bj;
            H1[bb * 256 + j] = (h > 0.f) ? h : expm1f(h);
        }
    }
    __syncthreads();
    {
        int j2 = tid & 127, g = tid >> 7;
        float acc[4] = {0.f, 0.f, 0.f, 0.f};
        for (int j = 0; j < 256; j++) {
            float w = W2[j * 128 + j2];
#pragma unroll
            for (int ii = 0; ii < 4; ii++) acc[ii] = fmaf(H1[(g * 4 + ii) * 256 + j], w, acc[ii]);
        }
        float bj = b2[j2];
#pragma unroll
        for (int ii = 0; ii < 4; ii++) {
            float h = acc[ii] + bj;
            H2[(g * 4 + ii) * 128 + j2] = (h > 0.f) ? h : expm1f(h);
        }
    }
    __syncthreads();
    {
        int wid = tid >> 5, lane = tid & 31;
        float s = 0.f;
        for (int j = lane; j < 128; j += 32) s = fmaf(H2[wid * 128 + j], W3[j], s);
        s = warp_sum(s);
        if (lane == 0) out[off + (size_t)(b0 + wid) * stride] = s + b3[0];
    }
}

// ---------------- orchestration ----------------
extern "C" void kernel_launch(void* const* d_in, const int* in_sizes, int n_in,
                              void* d_out, int out_size) {
    const float* emb     = (const float*)d_in[0];
    const float* keys    = (const float*)d_in[1];
    const float* memv    = (const float*)d_in[2];
    const float* W1      = (const float*)d_in[3];
    const float* b1      = (const float*)d_in[4];
    const float* W2      = (const float*)d_in[5];
    const float* b2      = (const float*)d_in[6];
    const float* W3      = (const float*)d_in[7];
    const float* b3      = (const float*)d_in[8];
    const int*   actions = (const int*)d_in[9];
    float* out = (float*)d_out;

    // normalized keys (once per launch) and initial normalized query
    row_denom_kernel<<<(Az * Nz + 255) / 256, 256>>>(keys, 0, Az * Nz);
    normalize_kernel<<<2048, 256>>>(keys, 0, (Az * Nz * Dz) / 4);
    row_denom_kernel<<<(Bsz + 255) / 256, 256>>>(emb, 1, Bsz);
    normalize_kernel<<<512, 256>>>(emb, 1, (Bsz * Dz) / 4);
    group_kernel<<<1, 256>>>(actions);

    // pred_values = MLP(embeddings) -> out[0..B)
    mlp_kernel<<<Bsz / 8, 256>>>(emb, 1, W1, b1, W2, b2, W3, b3, out, 0, 1);

    for (int t = 0; t < NSTEP; t++) {
        sims_gemm<<<dim3(Nz / 128, MT), 256>>>(t);
        topk_kernel<<<Bsz, 256>>>(memv, actions, t);
        // out[B + b*5 + t]
        mlp_kernel<<<Bsz / 8, 256>>>(emb, 0, W1, b1, W2, b2, W3, b3, out, Bsz + t, 5);
    }
}

// round 8
// speedup vs baseline: 1.2044x; 1.2044x over previous
#include <cuda_runtime.h>
#include <cuda_fp16.h>
#include <cstdint>
#include <math.h>

#define Bsz   1024
#define Az    5
#define Nz    16384
#define Dz    512
#define TOPK  50
#define NSTEP 5
#define MT    13          // max padded 128-row tiles
#define CAND_CAP 1024
#define MARGIN 0.02f

// ---- scratch (device globals, no allocations) ----
__device__ float  g_kn[(size_t)Az * Nz * Dz];     // 168 MB normalized keys (fp32, exact path)
__device__ __half g_kh[(size_t)Az * Nz * Dz];     // 84 MB normalized keys (fp16, approx path)
__device__ float  g_qn[Bsz * Dz];                 // normalized query fp32
__device__ __half g_qh[Bsz * Dz];                 // normalized query fp16
__device__ float  g_cur[Bsz * Dz];                // raw cur (MLP input)
__device__ __half g_simh[(size_t)Bsz * Nz];       // 32 MB approx sims
__device__ float  g_kdenom[Az * Nz];
__device__ float  g_qdenom[Bsz];
__device__ int    g_row_map[NSTEP][MT * 128];
__device__ int    g_tile_action[NSTEP][MT];

__device__ __forceinline__ float warp_sum(float v) {
#pragma unroll
    for (int o = 16; o; o >>= 1) v += __shfl_xor_sync(0xffffffffu, v, o);
    return v;
}

// Cephes/Eigen-style expf (fma Horner, Cody-Waite) — numerics frozen from passing round
__device__ __forceinline__ float ref_exp(float x) {
    float m = floorf(fmaf(x, 1.44269504088896341f, 0.5f));
    float r = fmaf(m, -0.693359375f, x);
    r = fmaf(m, 2.12194440e-4f, r);
    float r2 = r * r;
    float p = 1.9875691500E-4f;
    p = fmaf(p, r, 1.3981999507E-3f);
    p = fmaf(p, r, 8.3334519073E-3f);
    p = fmaf(p, r, 4.1665795894E-2f);
    p = fmaf(p, r, 1.6666665459E-1f);
    p = fmaf(p, r, 5.0000001201E-1f);
    float y = fmaf(p, r2, r) + 1.0f;
    return ldexpf(y, (int)m);
}

__device__ __forceinline__ unsigned hsort16(unsigned h) {   // half bits -> order-preserving u16
    return (h & 0x8000u) ? (0xFFFFu & ~h) : (h | 0x8000u);
}

// ---------------- row denominators: ||x|| + eps (8-accumulator vector-lane order) ----------------
__global__ void row_denom_kernel(const float* __restrict__ X, int which, int nrows) {
    int r = blockIdx.x * blockDim.x + threadIdx.x;
    if (r >= nrows) return;
    const float4* p = (const float4*)(X + (size_t)r * Dz);
    float a[8];
#pragma unroll
    for (int j = 0; j < 8; j++) a[j] = 0.f;
    for (int i = 0; i < Dz / 8; i++) {
        float4 v0 = p[2 * i];
        float4 v1 = p[2 * i + 1];
        a[0] = fmaf(v0.x, v0.x, a[0]); a[1] = fmaf(v0.y, v0.y, a[1]);
        a[2] = fmaf(v0.z, v0.z, a[2]); a[3] = fmaf(v0.w, v0.w, a[3]);
        a[4] = fmaf(v1.x, v1.x, a[4]); a[5] = fmaf(v1.y, v1.y, a[5]);
        a[6] = fmaf(v1.z, v1.z, a[6]); a[7] = fmaf(v1.w, v1.w, a[7]);
    }
    float e0 = a[0] + a[4], e1 = a[1] + a[5], e2 = a[2] + a[6], e3 = a[3] + a[7];
    float f0 = e0 + e2, f1 = e1 + e3;
    float d = __fsqrt_rn(f0 + f1) + 1e-8f;
    if (which) g_qdenom[r] = d; else g_kdenom[r] = d;
}

// ---------------- elementwise normalize (IEEE div) + fp16 pack ----------------
__global__ void normalize_kernel(const float* __restrict__ X, int which, int n4) {
    float* Y = which ? g_qn : g_kn;
    __half* Yh = which ? g_qh : g_kh;
    const float* D = which ? g_qdenom : g_kdenom;
    for (int i = blockIdx.x * blockDim.x + threadIdx.x; i < n4; i += gridDim.x * blockDim.x) {
        float4 v = ((const float4*)X)[i];
        float d = D[i >> 7];    // Dz/4 = 128 float4 per row
        float4 o;
        o.x = __fdiv_rn(v.x, d); o.y = __fdiv_rn(v.y, d);
        o.z = __fdiv_rn(v.z, d); o.w = __fdiv_rn(v.w, d);
        ((float4*)Y)[i] = o;
        __half2 h0 = __float22half2_rn(make_float2(o.x, o.y));
        __half2 h1 = __float22half2_rn(make_float2(o.z, o.w));
        uint2 pk;
        pk.x = *reinterpret_cast<unsigned*>(&h0);
        pk.y = *reinterpret_cast<unsigned*>(&h1);
        ((uint2*)Yh)[i] = pk;
    }
}

// ---------------- group batches by selected action, per step ----------------
__global__ void group_kernel(const int* __restrict__ actions) {
    __shared__ int cnt[Az], cur[Az];
    int tid = threadIdx.x;
    for (int t = 0; t < NSTEP; t++) {
        if (tid < Az) cnt[tid] = 0;
        __syncthreads();
        for (int b = tid; b < Bsz; b += blockDim.x)
            atomicAdd(&cnt[actions[b * NSTEP + t]], 1);
        __syncthreads();
        if (tid == 0) {
            int off = 0;
            for (int a = 0; a < Az; a++) {
                cur[a] = off;
                off += ((cnt[a] + 127) >> 7) << 7;
            }
        }
        __syncthreads();
        for (int i = tid; i < MT * 128; i += blockDim.x) g_row_map[t][i] = -1;
        __syncthreads();
        for (int b = tid; b < Bsz; b += blockDim.x) {
            int a = actions[b * NSTEP + t];
            int p = atomicAdd(&cur[a], 1);
            g_row_map[t][p] = b;
        }
        if (tid < MT) {
            int mt = tid, act = -1, off = 0;
            for (int a = 0; a < Az; a++) {
                int len = ((cnt[a] + 127) >> 7) << 7;
                if (mt * 128 >= off && mt * 128 < off + len) act = a;
                off += len;
            }
            g_tile_action[t][mt] = act;
        }
        __syncthreads();
    }
}

// ---------------- approximate fp16 GEMM (HFMA2, 2x FLOP rate) ----------------
// 128x128 tile, K chunk = 8 d (4 half2), 256 threads, 8x8 outputs/thread
__global__ __launch_bounds__(256, 2) void sims_approx(int t) {
    int mt = blockIdx.y;
    int act = g_tile_action[t][mt];
    if (act < 0) return;
    int n0 = blockIdx.x * 128;

    __shared__ unsigned As2[4][132];   // half2 words
    __shared__ unsigned Bs2[4][132];
    __shared__ int rs[128];

    int tid = threadIdx.x;
    if (tid < 128) rs[tid] = g_row_map[t][mt * 128 + tid];
    __syncthreads();

    int li = tid >> 1;          // 0..127
    int lk = tid & 1;           // which half of the 8-d chunk
    int arow = rs[li];
    const uint2* ap = (const uint2*)(g_qh + (size_t)(arow < 0 ? 0 : arow) * Dz);
    const uint2* bp = (const uint2*)(g_kh + ((size_t)act * Nz + n0 + li) * Dz);

    int tx = tid & 15, ty = tid >> 4;

    __half2 acc[8][8];
    __half2 hz = __float2half2_rn(0.f);
#pragma unroll
    for (int i = 0; i < 8; i++)
#pragma unroll
        for (int j = 0; j < 8; j++) acc[i][j] = hz;

    for (int k8 = 0; k8 < Dz / 8; k8++) {
        uint2 a = (arow >= 0) ? ap[2 * k8 + lk] : make_uint2(0u, 0u);
        uint2 b = bp[2 * k8 + lk];
        As2[lk * 2 + 0][li] = a.x; As2[lk * 2 + 1][li] = a.y;
        Bs2[lk * 2 + 0][li] = b.x; Bs2[lk * 2 + 1][li] = b.y;
        __syncthreads();
#pragma unroll
        for (int kk = 0; kk < 4; kk++) {
            unsigned a2[8], b2[8];
            *(uint4*)(a2)     = *(const uint4*)&As2[kk][ty * 4];
            *(uint4*)(a2 + 4) = *(const uint4*)&As2[kk][64 + ty * 4];
            *(uint4*)(b2)     = *(const uint4*)&Bs2[kk][tx * 4];
            *(uint4*)(b2 + 4) = *(const uint4*)&Bs2[kk][64 + tx * 4];
#pragma unroll
            for (int i = 0; i < 8; i++) {
                __half2 av = *reinterpret_cast<__half2*>(&a2[i]);
#pragma unroll
                for (int j = 0; j < 8; j++) {
                    __half2 bv = *reinterpret_cast<__half2*>(&b2[j]);
                    acc[i][j] = __hfma2(av, bv, acc[i][j]);
                }
            }
        }
        __syncthreads();
    }

#pragma unroll
    for (int i = 0; i < 8; i++) {
        int rl = (i < 4) ? (ty * 4 + i) : (64 + ty * 4 + i - 4);
        int r = rs[rl];
        if (r < 0) continue;
        __half* srow = g_simh + (size_t)r * Nz + n0;
#pragma unroll
        for (int j = 0; j < 8; j++) {
            int cl = (j < 4) ? (tx * 4 + j) : (64 + tx * 4 + j - 4);
            float s = __low2float(acc[i][j]) + __high2float(acc[i][j]);
            srow[cl] = __float2half_rn(s);
        }
    }
}

// ---------------- per-row: approx rank-50 threshold -> candidates -> exact rescoring ----------------
// -> exact top-50 (val desc, idx asc) -> reference softmax + gather (bit-identical to passing path)
__global__ __launch_bounds__(256) void topk_kernel(const float* __restrict__ memv,
                                                   const int* __restrict__ actions, int t) {
    __shared__ unsigned hist[1024];
    __shared__ int sh_bin, sh_r;
    __shared__ unsigned sh_T;
    __shared__ float4 s_q4[Dz / 4];
    __shared__ int   s_cidx[CAND_CAP];
    __shared__ float s_cval[CAND_CAP];
    __shared__ int   s_cnt;
    __shared__ float s_val[TOPK];
    __shared__ int   s_idx[TOPK];
    __shared__ float s_cur[Dz];
    __shared__ float s_acc8[8];
    __shared__ float sh_denom;

    int b = blockIdx.x;
    int tid = threadIdx.x;
    const uint4* srow8 = (const uint4*)(g_simh + (size_t)b * Nz);
    const __half* srowh = g_simh + (size_t)b * Nz;

    // ---- pass 1: histogram of top 10 sortable bits ----
    for (int i = tid; i < 1024; i += 256) hist[i] = 0u;
    __syncthreads();
    for (int i = tid; i < Nz / 8; i += 256) {
        uint4 v = srow8[i];
        unsigned w[4] = {v.x, v.y, v.z, v.w};
#pragma unroll
        for (int c = 0; c < 4; c++) {
            atomicAdd(&hist[hsort16(w[c] & 0xFFFFu) >> 6], 1u);
            atomicAdd(&hist[hsort16(w[c] >> 16) >> 6], 1u);
        }
    }
    __syncthreads();
    if (tid == 0) {
        int cum = 0, bin = 1023;
        for (; bin >= 0; bin--) {
            cum += (int)hist[bin];
            if (cum >= TOPK) break;
        }
        sh_bin = bin;
        sh_r = TOPK - (cum - (int)hist[bin]);
    }
    __syncthreads();
    unsigned bin1 = (unsigned)sh_bin;
    int r1 = sh_r;
    __syncthreads();

    // ---- pass 2: low 6 bits within the selected bin ----
    for (int i = tid; i < 64; i += 256) hist[i] = 0u;
    __syncthreads();
    for (int i = tid; i < Nz / 8; i += 256) {
        uint4 v = srow8[i];
        unsigned w[4] = {v.x, v.y, v.z, v.w};
#pragma unroll
        for (int c = 0; c < 4; c++) {
            unsigned s0 = hsort16(w[c] & 0xFFFFu);
            unsigned s1 = hsort16(w[c] >> 16);
            if ((s0 >> 6) == bin1) atomicAdd(&hist[s0 & 63u], 1u);
            if ((s1 >> 6) == bin1) atomicAdd(&hist[s1 & 63u], 1u);
        }
    }
    __syncthreads();
    if (tid == 0) {
        int cum = 0, l = 63;
        for (; l >= 0; l--) {
            cum += (int)hist[l];
            if (cum >= r1) break;
        }
        sh_T = (bin1 << 6) | (unsigned)l;
        s_cnt = 0;
    }
    __syncthreads();
    unsigned T16 = sh_T;
    // sortable -> half bits -> float threshold with safety margin
    unsigned hb = (T16 & 0x8000u) ? (T16 ^ 0x8000u) : (0xFFFFu & ~T16);
    __half hT = __ushort_as_half((unsigned short)hb);
    float Tf = __half2float(hT) - MARGIN;

    // load this row's qn into smem (for exact rescoring)
    for (int i = tid; i < Dz; i += 256)
        ((float*)s_q4)[i] = g_qn[(size_t)b * Dz + i];
    __syncthreads();

    // ---- pass 3: collect candidates ----
    for (int i = tid; i < Nz; i += 256) {
        float v = __half2float(srowh[i]);
        if (v >= Tf) {
            int p = atomicAdd(&s_cnt, 1);
            if (p < CAND_CAP) s_cidx[p] = i;
        }
    }
    __syncthreads();
    int C = min(s_cnt, CAND_CAP);

    // ---- pass 4: exact fp32 rescoring, d-ascending fmaf chain (bit-identical to r7 GEMM) ----
    int a = actions[b * NSTEP + t];
    const float* knb = g_kn + (size_t)a * Nz * Dz;
    for (int c = tid; c < C; c += 256) {
        const float4* kr = (const float4*)(knb + (size_t)s_cidx[c] * Dz);
        float acc = 0.f;
#pragma unroll 4
        for (int d4 = 0; d4 < Dz / 4; d4++) {
            float4 kv = __ldg(&kr[d4]);
            float4 qv = s_q4[d4];
            acc = fmaf(qv.x, kv.x, acc);
            acc = fmaf(qv.y, kv.y, acc);
            acc = fmaf(qv.z, kv.z, acc);
            acc = fmaf(qv.w, kv.w, acc);
        }
        s_cval[c] = acc;
    }
    __syncthreads();

    // ---- pass 5: exact ranking (value desc, index asc) into slots 0..49 ----
    for (int c = tid; c < C; c += 256) {
        float v = s_cval[c];
        int id = s_cidx[c];
        int rank = 0;
        for (int j = 0; j < C; j++) {
            float vj = s_cval[j];
            rank += (vj > v) || (vj == v && s_cidx[j] < id);
        }
        if (rank < TOPK) { s_val[rank] = v; s_idx[rank] = id; }
    }
    __syncthreads();

    // ---- pass 6: reference-ordered softmax (unchanged from passing kernel) ----
    if (tid == 0) {
        float mx = s_val[0];
        float sum = 0.f;
        for (int k2 = 0; k2 < TOPK; k2++) {
            float e = ref_exp(s_val[k2] - mx);
            s_val[k2] = e;
            sum += e;
        }
        for (int k2 = 0; k2 < TOPK; k2++) s_val[k2] = __fdiv_rn(s_val[k2], sum);
    }
    __syncthreads();

    // ---- pass 7: weighted gather (k-ascending fma), cur, norms, qn fp32 + fp16 ----
    const float* vb = memv + (size_t)a * Nz * Dz;
    float a0 = 0.f, a1 = 0.f;
    int d0 = tid, d1 = tid + 256;
    for (int k2 = 0; k2 < TOPK; k2++) {
        const float* vr = vb + (size_t)s_idx[k2] * Dz;
        float w2 = s_val[k2];
        a0 = fmaf(w2, vr[d0], a0);
        a1 = fmaf(w2, vr[d1], a1);
    }
    s_cur[d0] = a0;
    s_cur[d1] = a1;
    g_cur[b * Dz + d0] = a0;
    g_cur[b * Dz + d1] = a1;
    __syncthreads();

    if (tid < 8) {
        float acc = 0.f;
        for (int i = 0; i < Dz / 8; i++) {
            float x = s_cur[8 * i + tid];
            acc = fmaf(x, x, acc);
        }
        s_acc8[tid] = acc;
    }
    __syncthreads();
    if (tid == 0) {
        float e0 = s_acc8[0] + s_acc8[4], e1 = s_acc8[1] + s_acc8[5];
        float e2 = s_acc8[2] + s_acc8[6], e3 = s_acc8[3] + s_acc8[7];
        float f0 = e0 + e2, f1 = e1 + e3;
        sh_denom = __fsqrt_rn(f0 + f1) + 1e-8f;
    }
    __syncthreads();
    float dn = sh_denom;
    float q0 = __fdiv_rn(a0, dn);
    float q1 = __fdiv_rn(a1, dn);
    g_qn[b * Dz + d0] = q0;
    g_qn[b * Dz + d1] = q1;
    g_qh[b * Dz + d0] = __float2half_rn(q0);
    g_qh[b * Dz + d1] = __float2half_rn(q1);
}

// ---------------- fused 3-layer MLP (512->256->128->1, elu) ----------------
__global__ __launch_bounds__(256) void mlp_kernel(const float* __restrict__ emb, int use_emb,
                                                  const float* __restrict__ W1, const float* __restrict__ b1,
                                                  const float* __restrict__ W2, const float* __restrict__ b2,
                                                  const float* __restrict__ W3, const float* __restrict__ b3,
                                                  float* __restrict__ out, int off, int stride) {
    __shared__ float Xs[8 * 512];
    __shared__ float H1[8 * 256];
    __shared__ float H2[8 * 128];
    const float* X = use_emb ? emb : g_cur;
    int tid = threadIdx.x;
    int b0 = blockIdx.x * 8;

    for (int i = tid; i < 8 * 512; i += 256) Xs[i] = X[(size_t)b0 * 512 + i];
    __syncthreads();
    {
        int j = tid;
        float acc[8];
#pragma unroll
        for (int bb = 0; bb < 8; bb++) acc[bb] = 0.f;
        for (int d = 0; d < 512; d += 4) {
            float w0 = W1[(d + 0) * 256 + j];
            float w1 = W1[(d + 1) * 256 + j];
            float w2v = W1[(d + 2) * 256 + j];
            float w3v = W1[(d + 3) * 256 + j];
#pragma unroll
            for (int bb = 0; bb < 8; bb++) {
                float4 x = *(const float4*)(&Xs[bb * 512 + d]);
                acc[bb] = fmaf(x.x, w0, acc[bb]);
                acc[bb] = fmaf(x.y, w1, acc[bb]);
                acc[bb] = fmaf(x.z, w2v, acc[bb]);
                acc[bb] = fmaf(x.w, w3v, acc[bb]);
            }
        }
        float bj = b1[j];
#pragma unroll
        for (int bb = 0; bb < 8; bb++) {
            float h = acc[bb] + bj;
            H1[bb * 256 + j] = (h > 0.f) ? h : expm1f(h);
        }
    }
    __syncthreads();
    {
        int j2 = tid & 127, g = tid >> 7;
        float acc[4] = {0.f, 0.f, 0.f, 0.f};
        for (int j = 0; j < 256; j++) {
            float w = W2[j * 128 + j2];
#pragma unroll
            for (int ii = 0; ii < 4; ii++) acc[ii] = fmaf(H1[(g * 4 + ii) * 256 + j], w, acc[ii]);
        }
        float bj = b2[j2];
#pragma unroll
        for (int ii = 0; ii < 4; ii++) {
            float h = acc[ii] + bj;
            H2[(g * 4 + ii) * 128 + j2] = (h > 0.f) ? h : expm1f(h);
        }
    }
    __syncthreads();
    {
        int wid = tid >> 5, lane = tid & 31;
        float s = 0.f;
        for (int j = lane; j < 128; j += 32) s = fmaf(H2[wid * 128 + j], W3[j], s);
        s = warp_sum(s);
        if (lane == 0) out[off + (size_t)(b0 + wid) * stride] = s + b3[0];
    }
}

// ---------------- orchestration ----------------
extern "C" void kernel_launch(void* const* d_in, const int* in_sizes, int n_in,
                              void* d_out, int out_size) {
    const float* emb     = (const float*)d_in[0];
    const float* keys    = (const float*)d_in[1];
    const float* memv    = (const float*)d_in[2];
    const float* W1      = (const float*)d_in[3];
    const float* b1      = (const float*)d_in[4];
    const float* W2      = (const float*)d_in[5];
    const float* b2      = (const float*)d_in[6];
    const float* W3      = (const float*)d_in[7];
    const float* b3      = (const float*)d_in[8];
    const int*   actions = (const int*)d_in[9];
    float* out = (float*)d_out;

    row_denom_kernel<<<(Az * Nz + 255) / 256, 256>>>(keys, 0, Az * Nz);
    normalize_kernel<<<2048, 256>>>(keys, 0, (Az * Nz * Dz) / 4);
    row_denom_kernel<<<(Bsz + 255) / 256, 256>>>(emb, 1, Bsz);
    normalize_kernel<<<512, 256>>>(emb, 1, (Bsz * Dz) / 4);
    group_kernel<<<1, 256>>>(actions);

    mlp_kernel<<<Bsz / 8, 256>>>(emb, 1, W1, b1, W2, b2, W3, b3, out, 0, 1);

    for (int t = 0; t < NSTEP; t++) {
        sims_approx<<<dim3(Nz / 128, MT), 256>>>(t);
        topk_kernel<<<Bsz, 256>>>(memv, actions, t);
        mlp_kernel<<<Bsz / 8, 256>>>(emb, 0, W1, b1, W2, b2, W3, b3, out, Bsz + t, 5);
    }
}

// round 10
// speedup vs baseline: 2.2161x; 1.8399x over previous
#include <cuda_runtime.h>
#include <cuda_fp16.h>
#include <cstdint>
#include <math.h>

#define Bsz   1024
#define Az    5
#define Nz    16384
#define Dz    512
#define TOPK  50
#define NSTEP 5
#define MT    13          // max padded 128-row tiles
#define CAND_CAP 1024
#define MARGIN 0.006f

// ---- scratch (device globals, no allocations) ----
__device__ float  g_kn[(size_t)Az * Nz * Dz];     // fp32 normalized keys (exact path)
__device__ __half g_kh[(size_t)Az * Nz * Dz];     // fp16 normalized keys (MMA path)
__device__ float  g_qn[Bsz * Dz];
__device__ __half g_qh[Bsz * Dz];
__device__ float  g_cur[Bsz * Dz];
__device__ __half g_simh[(size_t)Bsz * Nz];       // 32 MB approx sims
__device__ float  g_kdenom[Az * Nz];
__device__ float  g_qdenom[Bsz];
__device__ int    g_row_map[NSTEP][MT * 128];
__device__ int    g_tile_action[NSTEP][MT];

__device__ __forceinline__ uint32_t smem_u32(const void* p) {
    uint32_t a;
    asm("{ .reg .u64 t; cvta.to.shared.u64 t, %1; cvt.u32.u64 %0, t; }" : "=r"(a) : "l"(p));
    return a;
}

#define SMEM_SWZ(off) ((off) ^ (((off) >> 3) & 0x70))

__device__ __forceinline__ void ldmatrix_x4(uint32_t* r, uint32_t addr) {
    asm volatile("ldmatrix.sync.aligned.m8n8.x4.shared.b16 {%0,%1,%2,%3}, [%4];"
                 : "=r"(r[0]), "=r"(r[1]), "=r"(r[2]), "=r"(r[3]) : "r"(addr));
}
__device__ __forceinline__ void mma_16816(float* c, const uint32_t* a, uint32_t b0, uint32_t b1) {
    asm volatile(
        "mma.sync.aligned.m16n8k16.row.col.f32.f16.f16.f32 "
        "{%0,%1,%2,%3}, {%4,%5,%6,%7}, {%8,%9}, {%0,%1,%2,%3};"
        : "+f"(c[0]), "+f"(c[1]), "+f"(c[2]), "+f"(c[3])
        : "r"(a[0]), "r"(a[1]), "r"(a[2]), "r"(a[3]), "r"(b0), "r"(b1));
}

__device__ __forceinline__ float warp_sum(float v) {
#pragma unroll
    for (int o = 16; o; o >>= 1) v += __shfl_xor_sync(0xffffffffu, v, o);
    return v;
}

// Cephes/Eigen-style expf — numerics frozen from passing round
__device__ __forceinline__ float ref_exp(float x) {
    float m = floorf(fmaf(x, 1.44269504088896341f, 0.5f));
    float r = fmaf(m, -0.693359375f, x);
    r = fmaf(m, 2.12194440e-4f, r);
    float r2 = r * r;
    float p = 1.9875691500E-4f;
    p = fmaf(p, r, 1.3981999507E-3f);
    p = fmaf(p, r, 8.3334519073E-3f);
    p = fmaf(p, r, 4.1665795894E-2f);
    p = fmaf(p, r, 1.6666665459E-1f);
    p = fmaf(p, r, 5.0000001201E-1f);
    float y = fmaf(p, r2, r) + 1.0f;
    return ldexpf(y, (int)m);
}

__device__ __forceinline__ unsigned hsort16(unsigned h) {
    return (h & 0x8000u) ? (0xFFFFu & ~h) : (h | 0x8000u);
}

// ---------------- row denominators ----------------
__global__ void row_denom_kernel(const float* __restrict__ X, int which, int nrows) {
    int r = blockIdx.x * blockDim.x + threadIdx.x;
    if (r >= nrows) return;
    const float4* p = (const float4*)(X + (size_t)r * Dz);
    float a[8];
#pragma unroll
    for (int j = 0; j < 8; j++) a[j] = 0.f;
    for (int i = 0; i < Dz / 8; i++) {
        float4 v0 = p[2 * i];
        float4 v1 = p[2 * i + 1];
        a[0] = fmaf(v0.x, v0.x, a[0]); a[1] = fmaf(v0.y, v0.y, a[1]);
        a[2] = fmaf(v0.z, v0.z, a[2]); a[3] = fmaf(v0.w, v0.w, a[3]);
        a[4] = fmaf(v1.x, v1.x, a[4]); a[5] = fmaf(v1.y, v1.y, a[5]);
        a[6] = fmaf(v1.z, v1.z, a[6]); a[7] = fmaf(v1.w, v1.w, a[7]);
    }
    float e0 = a[0] + a[4], e1 = a[1] + a[5], e2 = a[2] + a[6], e3 = a[3] + a[7];
    float f0 = e0 + e2, f1 = e1 + e3;
    float d = __fsqrt_rn(f0 + f1) + 1e-8f;
    if (which) g_qdenom[r] = d; else g_kdenom[r] = d;
}

// ---------------- normalize (IEEE div) + fp16 pack ----------------
__global__ void normalize_kernel(const float* __restrict__ X, int which, int n4) {
    float* Y = which ? g_qn : g_kn;
    __half* Yh = which ? g_qh : g_kh;
    const float* D = which ? g_qdenom : g_kdenom;
    for (int i = blockIdx.x * blockDim.x + threadIdx.x; i < n4; i += gridDim.x * blockDim.x) {
        float4 v = ((const float4*)X)[i];
        float d = D[i >> 7];
        float4 o;
        o.x = __fdiv_rn(v.x, d); o.y = __fdiv_rn(v.y, d);
        o.z = __fdiv_rn(v.z, d); o.w = __fdiv_rn(v.w, d);
        ((float4*)Y)[i] = o;
        __half2 h0 = __float22half2_rn(make_float2(o.x, o.y));
        __half2 h1 = __float22half2_rn(make_float2(o.z, o.w));
        uint2 pk;
        pk.x = *reinterpret_cast<unsigned*>(&h0);
        pk.y = *reinterpret_cast<unsigned*>(&h1);
        ((uint2*)Yh)[i] = pk;
    }
}

// ---------------- group batches by selected action ----------------
__global__ void group_kernel(const int* __restrict__ actions) {
    __shared__ int cnt[Az], cur[Az];
    int tid = threadIdx.x;
    for (int t = 0; t < NSTEP; t++) {
        if (tid < Az) cnt[tid] = 0;
        __syncthreads();
        for (int b = tid; b < Bsz; b += blockDim.x)
            atomicAdd(&cnt[actions[b * NSTEP + t]], 1);
        __syncthreads();
        if (tid == 0) {
            int off = 0;
            for (int a = 0; a < Az; a++) {
                cur[a] = off;
                off += ((cnt[a] + 127) >> 7) << 7;
            }
        }
        __syncthreads();
        for (int i = tid; i < MT * 128; i += blockDim.x) g_row_map[t][i] = -1;
        __syncthreads();
        for (int b = tid; b < Bsz; b += blockDim.x) {
            int a = actions[b * NSTEP + t];
            int p = atomicAdd(&cur[a], 1);
            g_row_map[t][p] = b;
        }
        if (tid < MT) {
            int mt = tid, act = -1, off = 0;
            for (int a = 0; a < Az; a++) {
                int len = ((cnt[a] + 127) >> 7) << 7;
                if (mt * 128 >= off && mt * 128 < off + len) act = a;
                off += len;
            }
            g_tile_action[t][mt] = act;
        }
        __syncthreads();
    }
}

// ---------------- mma.sync (HMMA) fp16 approx GEMM, fp32 accum ----------------
// CTA: D[128 q-rows x 128 keys]. 8 warps in 4(m) x 2(n) grid; warp tile 32x64.
// K=512 staged in 8 chunks of 64 halfs/row (SW128-swizzled smem, conflict-free ldmatrix).
__global__ __launch_bounds__(256, 2) void sims_mma(int t) {
    __shared__ __align__(1024) unsigned char sA[16384];
    __shared__ __align__(1024) unsigned char sB[16384];
    __shared__ int rs[128];

    int mt = blockIdx.y;
    int act = g_tile_action[t][mt];
    if (act < 0) return;
    int n0 = blockIdx.x * 128;

    int tid = threadIdx.x, wid = tid >> 5, lane = tid & 31;
    if (tid < 128) rs[tid] = g_row_map[t][mt * 128 + tid];
    __syncthreads();

    int warp_m = wid >> 1, warp_n = wid & 1;
    int m_base = warp_m * 32, nb_base = warp_n * 64;

    const uint4* qb = (const uint4*)g_qh;
    const uint4* kb = (const uint4*)(g_kh + ((size_t)act * Nz + n0) * Dz);

    uint32_t sA_u = smem_u32(sA), sB_u = smem_u32(sB);

    float c[2][8][4];
#pragma unroll
    for (int i = 0; i < 2; i++)
#pragma unroll
        for (int j = 0; j < 8; j++)
#pragma unroll
            for (int k = 0; k < 4; k++) c[i][j][k] = 0.f;

    // ldmatrix.x4 lane mapping: row_in_16 = lane&15, k-half = lane>>4
    int lrow = lane & 15;
    int lslot = lane >> 4;        // 0 or 1 (adds 8 halfs = 1 slot)

#pragma unroll 1
    for (int kc = 0; kc < 8; kc++) {
        // stage A and B chunks (64 halfs = 8 x 16B per row)
#pragma unroll
        for (int rep = 0; rep < 4; rep++) {
            int idx = tid + rep * 256;
            int row = idx >> 3, i4 = idx & 7;
            int ar = rs[row];
            uint4 va = (ar >= 0) ? qb[(size_t)ar * 64 + kc * 8 + i4] : make_uint4(0u, 0u, 0u, 0u);
            *(uint4*)(sA + SMEM_SWZ(row * 128 + i4 * 16)) = va;
            uint4 vbv = kb[(size_t)row * 64 + kc * 8 + i4];
            *(uint4*)(sB + SMEM_SWZ(row * 128 + i4 * 16)) = vbv;
        }
        __syncthreads();
#pragma unroll
        for (int k16 = 0; k16 < 4; k16++) {
            int slot16 = (2 * k16 + lslot) * 16;   // byte offset of this lane's 16B unit
            uint32_t a[2][4];
#pragma unroll
            for (int mi = 0; mi < 2; mi++) {
                int row = m_base + mi * 16 + lrow;
                uint32_t addr = sA_u + row * 128 + (slot16 ^ ((row & 7) << 4));
                ldmatrix_x4(a[mi], addr);
            }
            uint32_t bf[4][4];
#pragma unroll
            for (int nb = 0; nb < 4; nb++) {
                int row = nb_base + nb * 16 + lrow;
                uint32_t addr = sB_u + row * 128 + (slot16 ^ ((row & 7) << 4));
                ldmatrix_x4(bf[nb], addr);
            }
#pragma unroll
            for (int mi = 0; mi < 2; mi++)
#pragma unroll
                for (int nj = 0; nj < 8; nj++) {
                    int nb = nj >> 1, hi = nj & 1;
                    mma_16816(c[mi][nj], a[mi], bf[nb][hi], bf[nb][hi + 2]);
                }
        }
        __syncthreads();
    }

    // epilogue: c frag (m16n8): lane>>2 = row in 8-group, lane&3 -> col pair
#pragma unroll
    for (int mi = 0; mi < 2; mi++) {
        int r0 = rs[m_base + mi * 16 + (lane >> 2)];
        int r1 = rs[m_base + mi * 16 + (lane >> 2) + 8];
#pragma unroll
        for (int nj = 0; nj < 8; nj++) {
            int col = n0 + nb_base + nj * 8 + (lane & 3) * 2;
            if (r0 >= 0) {
                __half2 h = __floats2half2_rn(c[mi][nj][0], c[mi][nj][1]);
                *(unsigned*)(g_simh + (size_t)r0 * Nz + col) = *reinterpret_cast<unsigned*>(&h);
            }
            if (r1 >= 0) {
                __half2 h = __floats2half2_rn(c[mi][nj][2], c[mi][nj][3]);
                *(unsigned*)(g_simh + (size_t)r1 * Nz + col) = *reinterpret_cast<unsigned*>(&h);
            }
        }
    }
}

// ---------------- topk: approx threshold -> candidates -> exact rescoring -> softmax+gather ----------------
__global__ __launch_bounds__(256) void topk_kernel(const float* __restrict__ memv,
                                                   const int* __restrict__ actions, int t) {
    __shared__ unsigned hist[1024];
    __shared__ int sh_bin, sh_r;
    __shared__ unsigned sh_T;
    __shared__ float4 s_q4[Dz / 4];
    __shared__ int   s_cidx[CAND_CAP];
    __shared__ float s_cval[CAND_CAP];
    __shared__ int   s_cnt;
    __shared__ float s_val[TOPK];
    __shared__ int   s_idx[TOPK];
    __shared__ float s_cur[Dz];
    __shared__ float s_acc8[8];
    __shared__ float sh_denom;

    int b = blockIdx.x;
    int tid = threadIdx.x;
    const uint4* srow8 = (const uint4*)(g_simh + (size_t)b * Nz);
    const __half* srowh = g_simh + (size_t)b * Nz;

    for (int i = tid; i < 1024; i += 256) hist[i] = 0u;
    __syncthreads();
    for (int i = tid; i < Nz / 8; i += 256) {
        uint4 v = srow8[i];
        unsigned w[4] = {v.x, v.y, v.z, v.w};
#pragma unroll
        for (int c = 0; c < 4; c++) {
            atomicAdd(&hist[hsort16(w[c] & 0xFFFFu) >> 6], 1u);
            atomicAdd(&hist[hsort16(w[c] >> 16) >> 6], 1u);
        }
    }
    __syncthreads();
    if (tid == 0) {
        int cum = 0, bin = 1023;
        for (; bin >= 0; bin--) {
            cum += (int)hist[bin];
            if (cum >= TOPK) break;
        }
        sh_bin = bin;
        sh_r = TOPK - (cum - (int)hist[bin]);
    }
    __syncthreads();
    unsigned bin1 = (unsigned)sh_bin;
    int r1 = sh_r;
    __syncthreads();

    for (int i = tid; i < 64; i += 256) hist[i] = 0u;
    __syncthreads();
    for (int i = tid; i < Nz / 8; i += 256) {
        uint4 v = srow8[i];
        unsigned w[4] = {v.x, v.y, v.z, v.w};
#pragma unroll
        for (int c = 0; c < 4; c++) {
            unsigned s0 = hsort16(w[c] & 0xFFFFu);
            unsigned s1 = hsort16(w[c] >> 16);
            if ((s0 >> 6) == bin1) atomicAdd(&hist[s0 & 63u], 1u);
            if ((s1 >> 6) == bin1) atomicAdd(&hist[s1 & 63u], 1u);
        }
    }
    __syncthreads();
    if (tid == 0) {
        int cum = 0, l = 63;
        for (; l >= 0; l--) {
            cum += (int)hist[l];
            if (cum >= r1) break;
        }
        sh_T = (bin1 << 6) | (unsigned)l;
        s_cnt = 0;
    }
    __syncthreads();
    unsigned T16 = sh_T;
    unsigned hb = (T16 & 0x8000u) ? (T16 ^ 0x8000u) : (0xFFFFu & ~T16);
    __half hT = __ushort_as_half((unsigned short)hb);
    float Tf = __half2float(hT) - MARGIN;

    for (int i = tid; i < Dz; i += 256)
        ((float*)s_q4)[i] = g_qn[(size_t)b * Dz + i];
    __syncthreads();

    for (int i = tid; i < Nz; i += 256) {
        float v = __half2float(srowh[i]);
        if (v >= Tf) {
            int p = atomicAdd(&s_cnt, 1);
            if (p < CAND_CAP) s_cidx[p] = i;
        }
    }
    __syncthreads();
    int C = min(s_cnt, CAND_CAP);

    // exact fp32 rescoring, d-ascending fmaf chain (bit-identical to exact path)
    int a = actions[b * NSTEP + t];
    const float* knb = g_kn + (size_t)a * Nz * Dz;
    for (int c = tid; c < C; c += 256) {
        const float4* kr = (const float4*)(knb + (size_t)s_cidx[c] * Dz);
        float acc = 0.f;
#pragma unroll 4
        for (int d4 = 0; d4 < Dz / 4; d4++) {
            float4 kv = __ldg(&kr[d4]);
            float4 qv = s_q4[d4];
            acc = fmaf(qv.x, kv.x, acc);
            acc = fmaf(qv.y, kv.y, acc);
            acc = fmaf(qv.z, kv.z, acc);
            acc = fmaf(qv.w, kv.w, acc);
        }
        s_cval[c] = acc;
    }
    __syncthreads();

    for (int c = tid; c < C; c += 256) {
        float v = s_cval[c];
        int id = s_cidx[c];
        int rank = 0;
        for (int j = 0; j < C; j++) {
            float vj = s_cval[j];
            rank += (vj > v) || (vj == v && s_cidx[j] < id);
        }
        if (rank < TOPK) { s_val[rank] = v; s_idx[rank] = id; }
    }
    __syncthreads();

    if (tid == 0) {
        float mx = s_val[0];
        float sum = 0.f;
        for (int k2 = 0; k2 < TOPK; k2++) {
            float e = ref_exp(s_val[k2] - mx);
            s_val[k2] = e;
            sum += e;
        }
        for (int k2 = 0; k2 < TOPK; k2++) s_val[k2] = __fdiv_rn(s_val[k2], sum);
    }
    __syncthreads();

    const float* vb = memv + (size_t)a * Nz * Dz;
    float a0 = 0.f, a1 = 0.f;
    int d0 = tid, d1 = tid + 256;
    for (int k2 = 0; k2 < TOPK; k2++) {
        const float* vr = vb + (size_t)s_idx[k2] * Dz;
        float w2 = s_val[k2];
        a0 = fmaf(w2, vr[d0], a0);
        a1 = fmaf(w2, vr[d1], a1);
    }
    s_cur[d0] = a0;
    s_cur[d1] = a1;
    g_cur[b * Dz + d0] = a0;
    g_cur[b * Dz + d1] = a1;
    __syncthreads();

    if (tid < 8) {
        float acc = 0.f;
        for (int i = 0; i < Dz / 8; i++) {
            float x = s_cur[8 * i + tid];
            acc = fmaf(x, x, acc);
        }
        s_acc8[tid] = acc;
    }
    __syncthreads();
    if (tid == 0) {
        float e0 = s_acc8[0] + s_acc8[4], e1 = s_acc8[1] + s_acc8[5];
        float e2 = s_acc8[2] + s_acc8[6], e3 = s_acc8[3] + s_acc8[7];
        float f0 = e0 + e2, f1 = e1 + e3;
        sh_denom = __fsqrt_rn(f0 + f1) + 1e-8f;
    }
    __syncthreads();
    float dn = sh_denom;
    float q0 = __fdiv_rn(a0, dn);
    float q1 = __fdiv_rn(a1, dn);
    g_qn[b * Dz + d0] = q0;
    g_qn[b * Dz + d1] = q1;
    g_qh[b * Dz + d0] = __float2half_rn(q0);
    g_qh[b * Dz + d1] = __float2half_rn(q1);
}

// ---------------- fused 3-layer MLP (512->256->128->1, elu) ----------------
__global__ __launch_bounds__(256) void mlp_kernel(const float* __restrict__ emb, int use_emb,
                                                  const float* __restrict__ W1, const float* __restrict__ b1,
                                                  const float* __restrict__ W2, const float* __restrict__ b2,
                                                  const float* __restrict__ W3, const float* __restrict__ b3,
                                                  float* __restrict__ out, int off, int stride) {
    __shared__ float Xs[8 * 512];
    __shared__ float H1[8 * 256];
    __shared__ float H2[8 * 128];
    const float* X = use_emb ? emb : g_cur;
    int tid = threadIdx.x;
    int b0 = blockIdx.x * 8;

    for (int i = tid; i < 8 * 512; i += 256) Xs[i] = X[(size_t)b0 * 512 + i];
    __syncthreads();
    {
        int j = tid;
        float acc[8];
#pragma unroll
        for (int bb = 0; bb < 8; bb++) acc[bb] = 0.f;
        for (int d = 0; d < 512; d += 4) {
            float w0 = W1[(d + 0) * 256 + j];
            float w1 = W1[(d + 1) * 256 + j];
            float w2v = W1[(d + 2) * 256 + j];
            float w3v = W1[(d + 3) * 256 + j];
#pragma unroll
            for (int bb = 0; bb < 8; bb++) {
                float4 x = *(const float4*)(&Xs[bb * 512 + d]);
                acc[bb] = fmaf(x.x, w0, acc[bb]);
                acc[bb] = fmaf(x.y, w1, acc[bb]);
                acc[bb] = fmaf(x.z, w2v, acc[bb]);
                acc[bb] = fmaf(x.w, w3v, acc[bb]);
            }
        }
        float bj = b1[j];
#pragma unroll
        for (int bb = 0; bb < 8; bb++) {
            float h = acc[bb] + bj;
            H1[bb * 256 + j] = (h > 0.f) ? h : expm1f(h);
        }
    }
    __syncthreads();
    {
        int j2 = tid & 127, g = tid >> 7;
        float acc[4] = {0.f, 0.f, 0.f, 0.f};
        for (int j = 0; j < 256; j++) {
            float w = W2[j * 128 + j2];
#pragma unroll
            for (int ii = 0; ii < 4; ii++) acc[ii] = fmaf(H1[(g * 4 + ii) * 256 + j], w, acc[ii]);
        }
        float bj = b2[j2];
#pragma unroll
        for (int ii = 0; ii < 4; ii++) {
            float h = acc[ii] + bj;
            H2[(g * 4 + ii) * 128 + j2] = (h > 0.f) ? h : expm1f(h);
        }
    }
    __syncthreads();
    {
        int wid = tid >> 5, lane = tid & 31;
        float s = 0.f;
        for (int j = lane; j < 128; j += 32) s = fmaf(H2[wid * 128 + j], W3[j], s);
        s = warp_sum(s);
        if (lane == 0) out[off + (size_t)(b0 + wid) * stride] = s + b3[0];
    }
}

// ---------------- orchestration ----------------
extern "C" void kernel_launch(void* const* d_in, const int* in_sizes, int n_in,
                              void* d_out, int out_size) {
    const float* emb     = (const float*)d_in[0];
    const float* keys    = (const float*)d_in[1];
    const float* memv    = (const float*)d_in[2];
    const float* W1      = (const float*)d_in[3];
    const float* b1      = (const float*)d_in[4];
    const float* W2      = (const float*)d_in[5];
    const float* b2      = (const float*)d_in[6];
    const float* W3      = (const float*)d_in[7];
    const float* b3      = (const float*)d_in[8];
    const int*   actions = (const int*)d_in[9];
    float* out = (float*)d_out;

    row_denom_kernel<<<(Az * Nz + 255) / 256, 256>>>(keys, 0, Az * Nz);
    normalize_kernel<<<2048, 256>>>(keys, 0, (Az * Nz * Dz) / 4);
    row_denom_kernel<<<(Bsz + 255) / 256, 256>>>(emb, 1, Bsz);
    normalize_kernel<<<512, 256>>>(emb, 1, (Bsz * Dz) / 4);
    group_kernel<<<1, 256>>>(actions);

    mlp_kernel<<<Bsz / 8, 256>>>(emb, 1, W1, b1, W2, b2, W3, b3, out, 0, 1);

    for (int t = 0; t < NSTEP; t++) {
        sims_mma<<<dim3(Nz / 128, MT), 256>>>(t);
        topk_kernel<<<Bsz, 256>>>(memv, actions, t);
        mlp_kernel<<<Bsz / 8, 256>>>(emb, 0, W1, b1, W2, b2, W3, b3, out, Bsz + t, 5);
    }
}

// round 11
// speedup vs baseline: 2.8630x; 1.2920x over previous
#include <cuda_runtime.h>
#include <cuda_fp16.h>
#include <cstdint>
#include <math.h>

#define Bsz   1024
#define Az    5
#define Nz    16384
#define Dz    512
#define TOPK  50
#define NSTEP 5
#define MT    13          // max padded 128-row tiles
#define CAND_CAP 1024
#define MARGIN 0.006f
#define SIMS_DYN_SMEM (4 * 16384 + 1024)

// ---- scratch (device globals, no allocations) ----
__device__ float  g_kn[(size_t)Az * Nz * Dz];     // fp32 normalized keys (exact path)
__device__ __half g_kh[(size_t)Az * Nz * Dz];     // fp16 normalized keys (MMA path)
__device__ float  g_qn[Bsz * Dz];
__device__ __half g_qh[Bsz * Dz];
__device__ float  g_cur[Bsz * Dz];
__device__ __half g_simh[(size_t)Bsz * Nz];       // 32 MB approx sims
__device__ float  g_kdenom[Az * Nz];
__device__ float  g_qdenom[Bsz];
__device__ int    g_row_map[NSTEP][MT * 128];
__device__ int    g_tile_action[NSTEP][MT];

__device__ __forceinline__ uint32_t smem_u32(const void* p) {
    uint32_t a;
    asm("{ .reg .u64 t; cvta.to.shared.u64 t, %1; cvt.u32.u64 %0, t; }" : "=r"(a) : "l"(p));
    return a;
}

#define SMEM_SWZ(off) ((off) ^ (((off) >> 3) & 0x70))

__device__ __forceinline__ void cp_async16(uint32_t dst, const void* src, bool valid) {
    int sz = valid ? 16 : 0;
    asm volatile("cp.async.cg.shared.global [%0], [%1], 16, %2;"
                 :: "r"(dst), "l"(src), "r"(sz) : "memory");
}
#define CP_COMMIT() asm volatile("cp.async.commit_group;" ::: "memory")
#define CP_WAIT(n)  asm volatile("cp.async.wait_group %0;" :: "n"(n) : "memory")

__device__ __forceinline__ void ldmatrix_x4(uint32_t* r, uint32_t addr) {
    asm volatile("ldmatrix.sync.aligned.m8n8.x4.shared.b16 {%0,%1,%2,%3}, [%4];"
                 : "=r"(r[0]), "=r"(r[1]), "=r"(r[2]), "=r"(r[3]) : "r"(addr));
}
__device__ __forceinline__ void mma_16816(float* c, const uint32_t* a, uint32_t b0, uint32_t b1) {
    asm volatile(
        "mma.sync.aligned.m16n8k16.row.col.f32.f16.f16.f32 "
        "{%0,%1,%2,%3}, {%4,%5,%6,%7}, {%8,%9}, {%0,%1,%2,%3};"
        : "+f"(c[0]), "+f"(c[1]), "+f"(c[2]), "+f"(c[3])
        : "r"(a[0]), "r"(a[1]), "r"(a[2]), "r"(a[3]), "r"(b0), "r"(b1));
}

__device__ __forceinline__ float warp_sum(float v) {
#pragma unroll
    for (int o = 16; o; o >>= 1) v += __shfl_xor_sync(0xffffffffu, v, o);
    return v;
}

// Cephes/Eigen-style expf — numerics frozen from passing round
__device__ __forceinline__ float ref_exp(float x) {
    float m = floorf(fmaf(x, 1.44269504088896341f, 0.5f));
    float r = fmaf(m, -0.693359375f, x);
    r = fmaf(m, 2.12194440e-4f, r);
    float r2 = r * r;
    float p = 1.9875691500E-4f;
    p = fmaf(p, r, 1.3981999507E-3f);
    p = fmaf(p, r, 8.3334519073E-3f);
    p = fmaf(p, r, 4.1665795894E-2f);
    p = fmaf(p, r, 1.6666665459E-1f);
    p = fmaf(p, r, 5.0000001201E-1f);
    float y = fmaf(p, r2, r) + 1.0f;
    return ldexpf(y, (int)m);
}

__device__ __forceinline__ unsigned hsort16(unsigned h) {
    return (h & 0x8000u) ? (0xFFFFu & ~h) : (h | 0x8000u);
}

// ---------------- row denominators ----------------
__global__ void row_denom_kernel(const float* __restrict__ X, int which, int nrows) {
    int r = blockIdx.x * blockDim.x + threadIdx.x;
    if (r >= nrows) return;
    const float4* p = (const float4*)(X + (size_t)r * Dz);
    float a[8];
#pragma unroll
    for (int j = 0; j < 8; j++) a[j] = 0.f;
    for (int i = 0; i < Dz / 8; i++) {
        float4 v0 = p[2 * i];
        float4 v1 = p[2 * i + 1];
        a[0] = fmaf(v0.x, v0.x, a[0]); a[1] = fmaf(v0.y, v0.y, a[1]);
        a[2] = fmaf(v0.z, v0.z, a[2]); a[3] = fmaf(v0.w, v0.w, a[3]);
        a[4] = fmaf(v1.x, v1.x, a[4]); a[5] = fmaf(v1.y, v1.y, a[5]);
        a[6] = fmaf(v1.z, v1.z, a[6]); a[7] = fmaf(v1.w, v1.w, a[7]);
    }
    float e0 = a[0] + a[4], e1 = a[1] + a[5], e2 = a[2] + a[6], e3 = a[3] + a[7];
    float f0 = e0 + e2, f1 = e1 + e3;
    float d = __fsqrt_rn(f0 + f1) + 1e-8f;
    if (which) g_qdenom[r] = d; else g_kdenom[r] = d;
}

// ---------------- normalize (IEEE div) + fp16 pack ----------------
__global__ void normalize_kernel(const float* __restrict__ X, int which, int n4) {
    float* Y = which ? g_qn : g_kn;
    __half* Yh = which ? g_qh : g_kh;
    const float* D = which ? g_qdenom : g_kdenom;
    for (int i = blockIdx.x * blockDim.x + threadIdx.x; i < n4; i += gridDim.x * blockDim.x) {
        float4 v = ((const float4*)X)[i];
        float d = D[i >> 7];
        float4 o;
        o.x = __fdiv_rn(v.x, d); o.y = __fdiv_rn(v.y, d);
        o.z = __fdiv_rn(v.z, d); o.w = __fdiv_rn(v.w, d);
        ((float4*)Y)[i] = o;
        __half2 h0 = __float22half2_rn(make_float2(o.x, o.y));
        __half2 h1 = __float22half2_rn(make_float2(o.z, o.w));
        uint2 pk;
        pk.x = *reinterpret_cast<unsigned*>(&h0);
        pk.y = *reinterpret_cast<unsigned*>(&h1);
        ((uint2*)Yh)[i] = pk;
    }
}

// ---------------- group batches by selected action ----------------
__global__ void group_kernel(const int* __restrict__ actions) {
    __shared__ int cnt[Az], cur[Az];
    int tid = threadIdx.x;
    for (int t = 0; t < NSTEP; t++) {
        if (tid < Az) cnt[tid] = 0;
        __syncthreads();
        for (int b = tid; b < Bsz; b += blockDim.x)
            atomicAdd(&cnt[actions[b * NSTEP + t]], 1);
        __syncthreads();
        if (tid == 0) {
            int off = 0;
            for (int a = 0; a < Az; a++) {
                cur[a] = off;
                off += ((cnt[a] + 127) >> 7) << 7;
            }
        }
        __syncthreads();
        for (int i = tid; i < MT * 128; i += blockDim.x) g_row_map[t][i] = -1;
        __syncthreads();
        for (int b = tid; b < Bsz; b += blockDim.x) {
            int a = actions[b * NSTEP + t];
            int p = atomicAdd(&cur[a], 1);
            g_row_map[t][p] = b;
        }
        if (tid < MT) {
            int mt = tid, act = -1, off = 0;
            for (int a = 0; a < Az; a++) {
                int len = ((cnt[a] + 127) >> 7) << 7;
                if (mt * 128 >= off && mt * 128 < off + len) act = a;
                off += len;
            }
            g_tile_action[t][mt] = act;
        }
        __syncthreads();
    }
}

// ---------------- HMMA fp16 approx GEMM, fp32 accum, cp.async 2-stage pipeline ----------------
// CTA: D[128 q-rows x 128 keys]. 8 warps 4(m)x2(n); warp tile 32x64.
// K=512 in 8 chunks of 64 halfs/row, double-buffered via cp.async.
__global__ __launch_bounds__(256, 2) void sims_mma(int t) {
    extern __shared__ unsigned char dyn_smem[];
    __shared__ int rs[128];

    int mt = blockIdx.y;
    int act = g_tile_action[t][mt];
    if (act < 0) return;
    int n0 = blockIdx.x * 128;

    int tid = threadIdx.x, wid = tid >> 5, lane = tid & 31;
    if (tid < 128) rs[tid] = g_row_map[t][mt * 128 + tid];
    __syncthreads();

    unsigned char* base = (unsigned char*)(((uintptr_t)dyn_smem + 1023) & ~(uintptr_t)1023);
    uint32_t sAu[2] = { smem_u32(base),         smem_u32(base + 16384) };
    uint32_t sBu[2] = { smem_u32(base + 32768), smem_u32(base + 49152) };

    int warp_m = wid >> 1, warp_n = wid & 1;
    int m_base = warp_m * 32, nb_base = warp_n * 64;

    const uint4* qb = (const uint4*)g_qh;
    const uint4* kb = (const uint4*)(g_kh + ((size_t)act * Nz + n0) * Dz);

    float c[2][8][4];
#pragma unroll
    for (int i = 0; i < 2; i++)
#pragma unroll
        for (int j = 0; j < 8; j++)
#pragma unroll
            for (int k = 0; k < 4; k++) c[i][j][k] = 0.f;

    int lrow = lane & 15, lslot = lane >> 4;

    // per-thread fixed staging slots: 4 (row,i4) pairs
    int srow_[4], si4_[4], sar_[4];
    unsigned sw_[4];
#pragma unroll
    for (int rep = 0; rep < 4; rep++) {
        int idx = tid + rep * 256;
        srow_[rep] = idx >> 3;
        si4_[rep] = idx & 7;
        sar_[rep] = rs[srow_[rep]];
        sw_[rep] = SMEM_SWZ(srow_[rep] * 128 + si4_[rep] * 16);
    }

    auto stage = [&](int kc, int buf) {
#pragma unroll
        for (int rep = 0; rep < 4; rep++) {
            int ar = sar_[rep];
            cp_async16(sAu[buf] + sw_[rep],
                       qb + (size_t)(ar < 0 ? 0 : ar) * 64 + kc * 8 + si4_[rep], ar >= 0);
            cp_async16(sBu[buf] + sw_[rep],
                       kb + (size_t)srow_[rep] * 64 + kc * 8 + si4_[rep], true);
        }
        CP_COMMIT();
    };

    stage(0, 0);
#pragma unroll 1
    for (int kc = 0; kc < 8; kc++) {
        int buf = kc & 1;
        if (kc + 1 < 8) { stage(kc + 1, buf ^ 1); CP_WAIT(1); }
        else            { CP_WAIT(0); }
        __syncthreads();
#pragma unroll
        for (int k16 = 0; k16 < 4; k16++) {
            int slot16 = (2 * k16 + lslot) * 16;
            uint32_t a[2][4];
#pragma unroll
            for (int mi = 0; mi < 2; mi++) {
                int row = m_base + mi * 16 + lrow;
                ldmatrix_x4(a[mi], sAu[buf] + row * 128 + (slot16 ^ ((row & 7) << 4)));
            }
            uint32_t bf[4][4];
#pragma unroll
            for (int nb = 0; nb < 4; nb++) {
                int row = nb_base + nb * 16 + lrow;
                ldmatrix_x4(bf[nb], sBu[buf] + row * 128 + (slot16 ^ ((row & 7) << 4)));
            }
#pragma unroll
            for (int mi = 0; mi < 2; mi++)
#pragma unroll
                for (int nj = 0; nj < 8; nj++) {
                    int nb = nj >> 1, hi = nj & 1;
                    mma_16816(c[mi][nj], a[mi], bf[nb][hi], bf[nb][hi + 2]);
                }
        }
        __syncthreads();
    }

    // epilogue
#pragma unroll
    for (int mi = 0; mi < 2; mi++) {
        int r0 = rs[m_base + mi * 16 + (lane >> 2)];
        int r1 = rs[m_base + mi * 16 + (lane >> 2) + 8];
#pragma unroll
        for (int nj = 0; nj < 8; nj++) {
            int col = n0 + nb_base + nj * 8 + (lane & 3) * 2;
            if (r0 >= 0) {
                __half2 h = __floats2half2_rn(c[mi][nj][0], c[mi][nj][1]);
                *(unsigned*)(g_simh + (size_t)r0 * Nz + col) = *reinterpret_cast<unsigned*>(&h);
            }
            if (r1 >= 0) {
                __half2 h = __floats2half2_rn(c[mi][nj][2], c[mi][nj][3]);
                *(unsigned*)(g_simh + (size_t)r1 * Nz + col) = *reinterpret_cast<unsigned*>(&h);
            }
        }
    }
}

// ---------------- topk: 1-pass hist threshold -> candidates -> exact rescoring -> softmax+gather ----------------
__global__ __launch_bounds__(256) void topk_kernel(const float* __restrict__ memv,
                                                   const int* __restrict__ actions, int t) {
    __shared__ unsigned hist[1024];
    __shared__ int sh_bin;
    __shared__ float4 s_q4[Dz / 4];
    __shared__ int   s_cidx[CAND_CAP];
    __shared__ float s_cval[CAND_CAP];
    __shared__ int   s_cnt;
    __shared__ float s_val[TOPK];
    __shared__ int   s_idx[TOPK];
    __shared__ float s_cur[Dz];
    __shared__ float s_acc8[8];
    __shared__ float sh_denom;

    int b = blockIdx.x;
    int tid = threadIdx.x;
    const uint4* srow8 = (const uint4*)(g_simh + (size_t)b * Nz);

    // single 10-bit histogram pass
    for (int i = tid; i < 1024; i += 256) hist[i] = 0u;
    if (tid == 0) s_cnt = 0;
    __syncthreads();
    for (int i = tid; i < Nz / 8; i += 256) {
        uint4 v = srow8[i];
        unsigned w[4] = {v.x, v.y, v.z, v.w};
#pragma unroll
        for (int c = 0; c < 4; c++) {
            atomicAdd(&hist[hsort16(w[c] & 0xFFFFu) >> 6], 1u);
            atomicAdd(&hist[hsort16(w[c] >> 16) >> 6], 1u);
        }
    }
    __syncthreads();
    if (tid == 0) {
        int cum = 0, bin = 1023;
        for (; bin >= 0; bin--) {
            cum += (int)hist[bin];
            if (cum >= TOPK) break;
        }
        sh_bin = bin;
    }
    __syncthreads();
    // threshold = lower edge of the bin containing rank-50 (<= exact rank-50 value)
    unsigned T16 = ((unsigned)sh_bin) << 6;
    unsigned hb = (T16 & 0x8000u) ? (T16 ^ 0x8000u) : (0xFFFFu & ~T16);
    __half hT = __ushort_as_half((unsigned short)hb);
    float Tf = __half2float(hT) - MARGIN;

    for (int i = tid; i < Dz; i += 256)
        ((float*)s_q4)[i] = g_qn[(size_t)b * Dz + i];
    __syncthreads();

    // candidate collection (vectorized)
    for (int i8 = tid; i8 < Nz / 8; i8 += 256) {
        uint4 v = srow8[i8];
        unsigned w[4] = {v.x, v.y, v.z, v.w};
#pragma unroll
        for (int c2 = 0; c2 < 4; c2++) {
            float2 f = __half22float2(*reinterpret_cast<__half2*>(&w[c2]));
            if (f.x >= Tf) {
                int p = atomicAdd(&s_cnt, 1);
                if (p < CAND_CAP) s_cidx[p] = i8 * 8 + c2 * 2;
            }
            if (f.y >= Tf) {
                int p = atomicAdd(&s_cnt, 1);
                if (p < CAND_CAP) s_cidx[p] = i8 * 8 + c2 * 2 + 1;
            }
        }
    }
    __syncthreads();
    int C = min(s_cnt, CAND_CAP);

    // exact fp32 rescoring, d-ascending fmaf chain (bit-identical exact path)
    int a = actions[b * NSTEP + t];
    const float* knb = g_kn + (size_t)a * Nz * Dz;
    for (int c = tid; c < C; c += 256) {
        const float4* kr = (const float4*)(knb + (size_t)s_cidx[c] * Dz);
        float acc = 0.f;
#pragma unroll 4
        for (int d4 = 0; d4 < Dz / 4; d4++) {
            float4 kv = __ldg(&kr[d4]);
            float4 qv = s_q4[d4];
            acc = fmaf(qv.x, kv.x, acc);
            acc = fmaf(qv.y, kv.y, acc);
            acc = fmaf(qv.z, kv.z, acc);
            acc = fmaf(qv.w, kv.w, acc);
        }
        s_cval[c] = acc;
    }
    __syncthreads();

    // exact ranking (value desc, index asc) into slots 0..49
    for (int c = tid; c < C; c += 256) {
        float v = s_cval[c];
        int id = s_cidx[c];
        int rank = 0;
        for (int j = 0; j < C; j++) {
            float vj = s_cval[j];
            rank += (vj > v) || (vj == v && s_cidx[j] < id);
        }
        if (rank < TOPK) { s_val[rank] = v; s_idx[rank] = id; }
    }
    __syncthreads();

    if (tid == 0) {
        float mx = s_val[0];
        float sum = 0.f;
        for (int k2 = 0; k2 < TOPK; k2++) {
            float e = ref_exp(s_val[k2] - mx);
            s_val[k2] = e;
            sum += e;
        }
        for (int k2 = 0; k2 < TOPK; k2++) s_val[k2] = __fdiv_rn(s_val[k2], sum);
    }
    __syncthreads();

    const float* vb = memv + (size_t)a * Nz * Dz;
    float a0 = 0.f, a1 = 0.f;
    int d0 = tid, d1 = tid + 256;
    for (int k2 = 0; k2 < TOPK; k2++) {
        const float* vr = vb + (size_t)s_idx[k2] * Dz;
        float w2 = s_val[k2];
        a0 = fmaf(w2, vr[d0], a0);
        a1 = fmaf(w2, vr[d1], a1);
    }
    s_cur[d0] = a0;
    s_cur[d1] = a1;
    g_cur[b * Dz + d0] = a0;
    g_cur[b * Dz + d1] = a1;
    __syncthreads();

    if (tid < 8) {
        float acc = 0.f;
        for (int i = 0; i < Dz / 8; i++) {
            float x = s_cur[8 * i + tid];
            acc = fmaf(x, x, acc);
        }
        s_acc8[tid] = acc;
    }
    __syncthreads();
    if (tid == 0) {
        float e0 = s_acc8[0] + s_acc8[4], e1 = s_acc8[1] + s_acc8[5];
        float e2 = s_acc8[2] + s_acc8[6], e3 = s_acc8[3] + s_acc8[7];
        float f0 = e0 + e2, f1 = e1 + e3;
        sh_denom = __fsqrt_rn(f0 + f1) + 1e-8f;
    }
    __syncthreads();
    float dn = sh_denom;
    float q0 = __fdiv_rn(a0, dn);
    float q1 = __fdiv_rn(a1, dn);
    g_qn[b * Dz + d0] = q0;
    g_qn[b * Dz + d1] = q1;
    g_qh[b * Dz + d0] = __float2half_rn(q0);
    g_qh[b * Dz + d1] = __float2half_rn(q1);
}

// ---------------- fused 3-layer MLP (512->256->128->1, elu) ----------------
__global__ __launch_bounds__(256) void mlp_kernel(const float* __restrict__ emb, int use_emb,
                                                  const float* __restrict__ W1, const float* __restrict__ b1,
                                                  const float* __restrict__ W2, const float* __restrict__ b2,
                                                  const float* __restrict__ W3, const float* __restrict__ b3,
                                                  float* __restrict__ out, int off, int stride) {
    __shared__ float Xs[8 * 512];
    __shared__ float H1[8 * 256];
    __shared__ float H2[8 * 128];
    const float* X = use_emb ? emb : g_cur;
    int tid = threadIdx.x;
    int b0 = blockIdx.x * 8;

    for (int i = tid; i < 8 * 512; i += 256) Xs[i] = X[(size_t)b0 * 512 + i];
    __syncthreads();
    {
        int j = tid;
        float acc[8];
#pragma unroll
        for (int bb = 0; bb < 8; bb++) acc[bb] = 0.f;
        for (int d = 0; d < 512; d += 4) {
            float w0 = W1[(d + 0) * 256 + j];
            float w1 = W1[(d + 1) * 256 + j];
            float w2v = W1[(d + 2) * 256 + j];
            float w3v = W1[(d + 3) * 256 + j];
#pragma unroll
            for (int bb = 0; bb < 8; bb++) {
                float4 x = *(const float4*)(&Xs[bb * 512 + d]);
                acc[bb] = fmaf(x.x, w0, acc[bb]);
                acc[bb] = fmaf(x.y, w1, acc[bb]);
                acc[bb] = fmaf(x.z, w2v, acc[bb]);
                acc[bb] = fmaf(x.w, w3v, acc[bb]);
            }
        }
        float bj = b1[j];
#pragma unroll
        for (int bb = 0; bb < 8; bb++) {
            float h = acc[bb] + bj;
            H1[bb * 256 + j] = (h > 0.f) ? h : expm1f(h);
        }
    }
    __syncthreads();
    {
        int j2 = tid & 127, g = tid >> 7;
        float acc[4] = {0.f, 0.f, 0.f, 0.f};
        for (int j = 0; j < 256; j++) {
            float w = W2[j * 128 + j2];
#pragma unroll
            for (int ii = 0; ii < 4; ii++) acc[ii] = fmaf(H1[(g * 4 + ii) * 256 + j], w, acc[ii]);
        }
        float bj = b2[j2];
#pragma unroll
        for (int ii = 0; ii < 4; ii++) {
            float h = acc[ii] + bj;
            H2[(g * 4 + ii) * 128 + j2] = (h > 0.f) ? h : expm1f(h);
        }
    }
    __syncthreads();
    {
        int wid = tid >> 5, lane = tid & 31;
        float s = 0.f;
        for (int j = lane; j < 128; j += 32) s = fmaf(H2[wid * 128 + j], W3[j], s);
        s = warp_sum(s);
        if (lane == 0) out[off + (size_t)(b0 + wid) * stride] = s + b3[0];
    }
}

// ---------------- orchestration ----------------
extern "C" void kernel_launch(void* const* d_in, const int* in_sizes, int n_in,
                              void* d_out, int out_size) {
    const float* emb     = (const float*)d_in[0];
    const float* keys    = (const float*)d_in[1];
    const float* memv    = (const float*)d_in[2];
    const float* W1      = (const float*)d_in[3];
    const float* b1      = (const float*)d_in[4];
    const float* W2      = (const float*)d_in[5];
    const float* b2      = (const float*)d_in[6];
    const float* W3      = (const float*)d_in[7];
    const float* b3      = (const float*)d_in[8];
    const int*   actions = (const int*)d_in[9];
    float* out = (float*)d_out;

    cudaFuncSetAttribute(sims_mma, cudaFuncAttributeMaxDynamicSharedMemorySize, SIMS_DYN_SMEM);

    row_denom_kernel<<<(Az * Nz + 255) / 256, 256>>>(keys, 0, Az * Nz);
    normalize_kernel<<<2048, 256>>>(keys, 0, (Az * Nz * Dz) / 4);
    row_denom_kernel<<<(Bsz + 255) / 256, 256>>>(emb, 1, Bsz);
    normalize_kernel<<<512, 256>>>(emb, 1, (Bsz * Dz) / 4);
    group_kernel<<<1, 256>>>(actions);

    mlp_kernel<<<Bsz / 8, 256>>>(emb, 1, W1, b1, W2, b2, W3, b3, out, 0, 1);

    for (int t = 0; t < NSTEP; t++) {
        sims_mma<<<dim3(Nz / 128, MT), 256, SIMS_DYN_SMEM>>>(t);
        topk_kernel<<<Bsz, 256>>>(memv, actions, t);
        mlp_kernel<<<Bsz / 8, 256>>>(emb, 0, W1, b1, W2, b2, W3, b3, out, Bsz + t, 5);
    }
}

// round 12
// speedup vs baseline: 2.9165x; 1.0187x over previous
#include <cuda_runtime.h>
#include <cuda_fp16.h>
#include <cstdint>
#include <math.h>

#define Bsz   1024
#define Az    5
#define Nz    16384
#define Dz    512
#define TOPK  50
#define NSTEP 5
#define MT    13          // max padded 128-row tiles
#define CAND_CAP 1024
#define MARGIN 0.006f
#define SIMS_DYN_SMEM (4 * 16384 + 1024)

// ---- scratch (device globals, no allocations) ----
__device__ float  g_kn[(size_t)Az * Nz * Dz];     // fp32 normalized keys (exact path)
__device__ __half g_kh[(size_t)Az * Nz * Dz];     // fp16 normalized keys (MMA path)
__device__ float  g_qn[Bsz * Dz];
__device__ __half g_qh[Bsz * Dz];
__device__ float  g_cur[Bsz * Dz];
__device__ __half g_simh[(size_t)Bsz * Nz];       // 32 MB approx sims
__device__ unsigned g_bmaxkey[Bsz * 128];         // per (row, 128-col block) max (sortable u16 key)
__device__ float  g_kdenom[Az * Nz];
__device__ float  g_qdenom[Bsz];
__device__ int    g_row_map[NSTEP][MT * 128];
__device__ int    g_tile_action[NSTEP][MT];

__device__ __forceinline__ uint32_t smem_u32(const void* p) {
    uint32_t a;
    asm("{ .reg .u64 t; cvta.to.shared.u64 t, %1; cvt.u32.u64 %0, t; }" : "=r"(a) : "l"(p));
    return a;
}

#define SMEM_SWZ(off) ((off) ^ (((off) >> 3) & 0x70))

__device__ __forceinline__ void cp_async16(uint32_t dst, const void* src, bool valid) {
    int sz = valid ? 16 : 0;
    asm volatile("cp.async.cg.shared.global [%0], [%1], 16, %2;"
                 :: "r"(dst), "l"(src), "r"(sz) : "memory");
}
#define CP_COMMIT() asm volatile("cp.async.commit_group;" ::: "memory")
#define CP_WAIT(n)  asm volatile("cp.async.wait_group %0;" :: "n"(n) : "memory")

__device__ __forceinline__ void ldmatrix_x4(uint32_t* r, uint32_t addr) {
    asm volatile("ldmatrix.sync.aligned.m8n8.x4.shared.b16 {%0,%1,%2,%3}, [%4];"
                 : "=r"(r[0]), "=r"(r[1]), "=r"(r[2]), "=r"(r[3]) : "r"(addr));
}
__device__ __forceinline__ void mma_16816(float* c, const uint32_t* a, uint32_t b0, uint32_t b1) {
    asm volatile(
        "mma.sync.aligned.m16n8k16.row.col.f32.f16.f16.f32 "
        "{%0,%1,%2,%3}, {%4,%5,%6,%7}, {%8,%9}, {%0,%1,%2,%3};"
        : "+f"(c[0]), "+f"(c[1]), "+f"(c[2]), "+f"(c[3])
        : "r"(a[0]), "r"(a[1]), "r"(a[2]), "r"(a[3]), "r"(b0), "r"(b1));
}

__device__ __forceinline__ float warp_sum(float v) {
#pragma unroll
    for (int o = 16; o; o >>= 1) v += __shfl_xor_sync(0xffffffffu, v, o);
    return v;
}

// Cephes/Eigen-style expf — numerics frozen from passing round
__device__ __forceinline__ float ref_exp(float x) {
    float m = floorf(fmaf(x, 1.44269504088896341f, 0.5f));
    float r = fmaf(m, -0.693359375f, x);
    r = fmaf(m, 2.12194440e-4f, r);
    float r2 = r * r;
    float p = 1.9875691500E-4f;
    p = fmaf(p, r, 1.3981999507E-3f);
    p = fmaf(p, r, 8.3334519073E-3f);
    p = fmaf(p, r, 4.1665795894E-2f);
    p = fmaf(p, r, 1.6666665459E-1f);
    p = fmaf(p, r, 5.0000001201E-1f);
    float y = fmaf(p, r2, r) + 1.0f;
    return ldexpf(y, (int)m);
}

__device__ __forceinline__ unsigned hsort16(unsigned h) {
    return (h & 0x8000u) ? (0xFFFFu & ~h) : (h | 0x8000u);
}
__device__ __forceinline__ float hkey2float(unsigned k) {
    unsigned hb = (k & 0x8000u) ? (k ^ 0x8000u) : (0xFFFFu & ~k);
    return __half2float(__ushort_as_half((unsigned short)hb));
}

// ---------------- row denominators ----------------
__global__ void row_denom_kernel(const float* __restrict__ X, int which, int nrows) {
    int r = blockIdx.x * blockDim.x + threadIdx.x;
    if (r >= nrows) return;
    const float4* p = (const float4*)(X + (size_t)r * Dz);
    float a[8];
#pragma unroll
    for (int j = 0; j < 8; j++) a[j] = 0.f;
    for (int i = 0; i < Dz / 8; i++) {
        float4 v0 = p[2 * i];
        float4 v1 = p[2 * i + 1];
        a[0] = fmaf(v0.x, v0.x, a[0]); a[1] = fmaf(v0.y, v0.y, a[1]);
        a[2] = fmaf(v0.z, v0.z, a[2]); a[3] = fmaf(v0.w, v0.w, a[3]);
        a[4] = fmaf(v1.x, v1.x, a[4]); a[5] = fmaf(v1.y, v1.y, a[5]);
        a[6] = fmaf(v1.z, v1.z, a[6]); a[7] = fmaf(v1.w, v1.w, a[7]);
    }
    float e0 = a[0] + a[4], e1 = a[1] + a[5], e2 = a[2] + a[6], e3 = a[3] + a[7];
    float f0 = e0 + e2, f1 = e1 + e3;
    float d = __fsqrt_rn(f0 + f1) + 1e-8f;
    if (which) g_qdenom[r] = d; else g_kdenom[r] = d;
}

// ---------------- normalize (IEEE div) + fp16 pack ----------------
__global__ void normalize_kernel(const float* __restrict__ X, int which, int n4) {
    float* Y = which ? g_qn : g_kn;
    __half* Yh = which ? g_qh : g_kh;
    const float* D = which ? g_qdenom : g_kdenom;
    for (int i = blockIdx.x * blockDim.x + threadIdx.x; i < n4; i += gridDim.x * blockDim.x) {
        float4 v = ((const float4*)X)[i];
        float d = D[i >> 7];
        float4 o;
        o.x = __fdiv_rn(v.x, d); o.y = __fdiv_rn(v.y, d);
        o.z = __fdiv_rn(v.z, d); o.w = __fdiv_rn(v.w, d);
        ((float4*)Y)[i] = o;
        __half2 h0 = __float22half2_rn(make_float2(o.x, o.y));
        __half2 h1 = __float22half2_rn(make_float2(o.z, o.w));
        uint2 pk;
        pk.x = *reinterpret_cast<unsigned*>(&h0);
        pk.y = *reinterpret_cast<unsigned*>(&h1);
        ((uint2*)Yh)[i] = pk;
    }
}

// ---------------- group batches by selected action ----------------
__global__ void group_kernel(const int* __restrict__ actions) {
    __shared__ int cnt[Az], cur[Az];
    int tid = threadIdx.x;
    for (int t = 0; t < NSTEP; t++) {
        if (tid < Az) cnt[tid] = 0;
        __syncthreads();
        for (int b = tid; b < Bsz; b += blockDim.x)
            atomicAdd(&cnt[actions[b * NSTEP + t]], 1);
        __syncthreads();
        if (tid == 0) {
            int off = 0;
            for (int a = 0; a < Az; a++) {
                cur[a] = off;
                off += ((cnt[a] + 127) >> 7) << 7;
            }
        }
        __syncthreads();
        for (int i = tid; i < MT * 128; i += blockDim.x) g_row_map[t][i] = -1;
        __syncthreads();
        for (int b = tid; b < Bsz; b += blockDim.x) {
            int a = actions[b * NSTEP + t];
            int p = atomicAdd(&cur[a], 1);
            g_row_map[t][p] = b;
        }
        if (tid < MT) {
            int mt = tid, act = -1, off = 0;
            for (int a = 0; a < Az; a++) {
                int len = ((cnt[a] + 127) >> 7) << 7;
                if (mt * 128 >= off && mt * 128 < off + len) act = a;
                off += len;
            }
            g_tile_action[t][mt] = act;
        }
        __syncthreads();
    }
}

// ---------------- HMMA fp16 approx GEMM + per-block row maxes ----------------
__global__ __launch_bounds__(256, 2) void sims_mma(int t) {
    extern __shared__ unsigned char dyn_smem[];
    __shared__ int rs[128];
    __shared__ unsigned s_rmax[2][128];

    int mt = blockIdx.y;
    int act = g_tile_action[t][mt];
    if (act < 0) return;
    int n0 = blockIdx.x * 128;

    int tid = threadIdx.x, wid = tid >> 5, lane = tid & 31;
    if (tid < 128) rs[tid] = g_row_map[t][mt * 128 + tid];
    __syncthreads();

    unsigned char* base = (unsigned char*)(((uintptr_t)dyn_smem + 1023) & ~(uintptr_t)1023);
    uint32_t sAu[2] = { smem_u32(base),         smem_u32(base + 16384) };
    uint32_t sBu[2] = { smem_u32(base + 32768), smem_u32(base + 49152) };

    int warp_m = wid >> 1, warp_n = wid & 1;
    int m_base = warp_m * 32, nb_base = warp_n * 64;

    const uint4* qb = (const uint4*)g_qh;
    const uint4* kb = (const uint4*)(g_kh + ((size_t)act * Nz + n0) * Dz);

    float c[2][8][4];
#pragma unroll
    for (int i = 0; i < 2; i++)
#pragma unroll
        for (int j = 0; j < 8; j++)
#pragma unroll
            for (int k = 0; k < 4; k++) c[i][j][k] = 0.f;

    int lrow = lane & 15, lslot = lane >> 4;

    int srow_[4], si4_[4], sar_[4];
    unsigned sw_[4];
#pragma unroll
    for (int rep = 0; rep < 4; rep++) {
        int idx = tid + rep * 256;
        srow_[rep] = idx >> 3;
        si4_[rep] = idx & 7;
        sar_[rep] = rs[srow_[rep]];
        sw_[rep] = SMEM_SWZ(srow_[rep] * 128 + si4_[rep] * 16);
    }

    auto stage = [&](int kc, int buf) {
#pragma unroll
        for (int rep = 0; rep < 4; rep++) {
            int ar = sar_[rep];
            cp_async16(sAu[buf] + sw_[rep],
                       qb + (size_t)(ar < 0 ? 0 : ar) * 64 + kc * 8 + si4_[rep], ar >= 0);
            cp_async16(sBu[buf] + sw_[rep],
                       kb + (size_t)srow_[rep] * 64 + kc * 8 + si4_[rep], true);
        }
        CP_COMMIT();
    };

    stage(0, 0);
#pragma unroll 1
    for (int kc = 0; kc < 8; kc++) {
        int buf = kc & 1;
        if (kc + 1 < 8) { stage(kc + 1, buf ^ 1); CP_WAIT(1); }
        else            { CP_WAIT(0); }
        __syncthreads();
#pragma unroll
        for (int k16 = 0; k16 < 4; k16++) {
            int slot16 = (2 * k16 + lslot) * 16;
            uint32_t a[2][4];
#pragma unroll
            for (int mi = 0; mi < 2; mi++) {
                int row = m_base + mi * 16 + lrow;
                ldmatrix_x4(a[mi], sAu[buf] + row * 128 + (slot16 ^ ((row & 7) << 4)));
            }
            uint32_t bf[4][4];
#pragma unroll
            for (int nb = 0; nb < 4; nb++) {
                int row = nb_base + nb * 16 + lrow;
                ldmatrix_x4(bf[nb], sBu[buf] + row * 128 + (slot16 ^ ((row & 7) << 4)));
            }
#pragma unroll
            for (int mi = 0; mi < 2; mi++)
#pragma unroll
                for (int nj = 0; nj < 8; nj++) {
                    int nb = nj >> 1, hi = nj & 1;
                    mma_16816(c[mi][nj], a[mi], bf[nb][hi], bf[nb][hi + 2]);
                }
        }
        __syncthreads();
    }

    // epilogue: store half sims + per-row block-max keys
    unsigned km[2][2];
    km[0][0] = km[0][1] = km[1][0] = km[1][1] = 0u;
#pragma unroll
    for (int mi = 0; mi < 2; mi++) {
        int r0 = rs[m_base + mi * 16 + (lane >> 2)];
        int r1 = rs[m_base + mi * 16 + (lane >> 2) + 8];
#pragma unroll
        for (int nj = 0; nj < 8; nj++) {
            int col = n0 + nb_base + nj * 8 + (lane & 3) * 2;
            __half2 h0 = __floats2half2_rn(c[mi][nj][0], c[mi][nj][1]);
            __half2 h1 = __floats2half2_rn(c[mi][nj][2], c[mi][nj][3]);
            unsigned u0 = *reinterpret_cast<unsigned*>(&h0);
            unsigned u1 = *reinterpret_cast<unsigned*>(&h1);
            km[mi][0] = max(km[mi][0], max(hsort16(u0 & 0xFFFFu), hsort16(u0 >> 16)));
            km[mi][1] = max(km[mi][1], max(hsort16(u1 & 0xFFFFu), hsort16(u1 >> 16)));
            if (r0 >= 0) *(unsigned*)(g_simh + (size_t)r0 * Nz + col) = u0;
            if (r1 >= 0) *(unsigned*)(g_simh + (size_t)r1 * Nz + col) = u1;
        }
    }
#pragma unroll
    for (int mi = 0; mi < 2; mi++)
#pragma unroll
        for (int rr = 0; rr < 2; rr++) {
            unsigned v = km[mi][rr];
            v = max(v, __shfl_xor_sync(0xffffffffu, v, 1));
            v = max(v, __shfl_xor_sync(0xffffffffu, v, 2));
            if ((lane & 3) == 0)
                s_rmax[warp_n][m_base + mi * 16 + (lane >> 2) + rr * 8] = v;
        }
    __syncthreads();
    if (tid < 128) {
        int r = rs[tid];
        if (r >= 0)
            g_bmaxkey[r * 128 + blockIdx.x] = max(s_rmax[0][tid], s_rmax[1][tid]);
    }
}

// ---------------- topk: block-max threshold -> 1 scan -> a50 refine -> exact rescoring ----------------
__global__ __launch_bounds__(256) void topk_kernel(const float* __restrict__ memv,
                                                   const int* __restrict__ actions, int t) {
    __shared__ unsigned s_bk[128];
    __shared__ unsigned char s_skip[128];
    __shared__ unsigned sh_T0, sh_a50;
    __shared__ float4 s_q4[Dz / 4];
    __shared__ int   s_cidx[CAND_CAP];
    __shared__ float s_cvala[CAND_CAP];   // approx values
    __shared__ float s_cval[CAND_CAP];    // exact values (or -inf)
    __shared__ int   s_cnt;
    __shared__ float s_val[TOPK];
    __shared__ int   s_idx[TOPK];
    __shared__ float s_cur[Dz];
    __shared__ float s_acc8[8];
    __shared__ float sh_denom;

    int b = blockIdx.x;
    int tid = threadIdx.x;
    const uint4* srow8 = (const uint4*)(g_simh + (size_t)b * Nz);

    if (tid == 0) { s_cnt = 0; sh_T0 = 0xFFFFFFFFu; sh_a50 = 0xFFFFFFFFu; }
    if (tid < 128) s_bk[tid] = g_bmaxkey[b * 128 + tid];
    for (int i = tid; i < Dz; i += 256)
        ((float*)s_q4)[i] = g_qn[(size_t)b * Dz + i];
    __syncthreads();

    // 50th-largest block max (M50 <= row's rank-50 value)
    if (tid < 128) {
        unsigned v = s_bk[tid];
        int cg = 0;
        for (int j = 0; j < 128; j++) cg += (s_bk[j] > v);
        if (cg <= 49) atomicMin(&sh_T0, v);
    }
    __syncthreads();
    float Tf = hkey2float(sh_T0) - MARGIN;
    if (tid < 128) s_skip[tid] = (hkey2float(s_bk[tid]) < Tf) ? 1 : 0;
    __syncthreads();

    // single candidate scan with block skipping
    for (int i8 = tid; i8 < Nz / 8; i8 += 256) {
        if (s_skip[i8 >> 4]) continue;
        uint4 v = srow8[i8];
        unsigned w[4] = {v.x, v.y, v.z, v.w};
#pragma unroll
        for (int c2 = 0; c2 < 4; c2++) {
            float2 f = __half22float2(*reinterpret_cast<__half2*>(&w[c2]));
            if (f.x >= Tf) {
                int p = atomicAdd(&s_cnt, 1);
                if (p < CAND_CAP) { s_cidx[p] = i8 * 8 + c2 * 2; s_cvala[p] = f.x; }
            }
            if (f.y >= Tf) {
                int p = atomicAdd(&s_cnt, 1);
                if (p < CAND_CAP) { s_cidx[p] = i8 * 8 + c2 * 2 + 1; s_cvala[p] = f.y; }
            }
        }
    }
    __syncthreads();
    int C = min(s_cnt, CAND_CAP);

    // a50 = 50th-largest approx value among candidates (== global approx rank-50)
    for (int c = tid; c < C; c += 256) {
        float v = s_cvala[c];
        int cg = 0;
        for (int j = 0; j < C; j++) cg += (s_cvala[j] > v);
        if (cg <= 49) {
            unsigned u = __float_as_uint(v);
            u = (u & 0x80000000u) ? ~u : (u | 0x80000000u);
            atomicMin(&sh_a50, u);
        }
    }
    __syncthreads();
    unsigned ua = sh_a50;
    ua = (ua & 0x80000000u) ? (ua ^ 0x80000000u) : ~ua;
    float ft = __uint_as_float(ua) - MARGIN;

    // exact fp32 rescoring of the refined set (d-ascending fmaf chain, frozen numerics)
    int a = actions[b * NSTEP + t];
    const float* knb = g_kn + (size_t)a * Nz * Dz;
    for (int c = tid; c < C; c += 256) {
        if (s_cvala[c] < ft) { s_cval[c] = -3.4e38f; continue; }
        const float4* kr = (const float4*)(knb + (size_t)s_cidx[c] * Dz);
        float acc = 0.f;
#pragma unroll 4
        for (int d4 = 0; d4 < Dz / 4; d4++) {
            float4 kv = __ldg(&kr[d4]);
            float4 qv = s_q4[d4];
            acc = fmaf(qv.x, kv.x, acc);
            acc = fmaf(qv.y, kv.y, acc);
            acc = fmaf(qv.z, kv.z, acc);
            acc = fmaf(qv.w, kv.w, acc);
        }
        s_cval[c] = acc;
    }
    __syncthreads();

    // exact ranking (value desc, index asc) into slots 0..49
    for (int c = tid; c < C; c += 256) {
        float v = s_cval[c];
        int id = s_cidx[c];
        int rank = 0;
        for (int j = 0; j < C; j++) {
            float vj = s_cval[j];
            rank += (vj > v) || (vj == v && s_cidx[j] < id);
        }
        if (rank < TOPK) { s_val[rank] = v; s_idx[rank] = id; }
    }
    __syncthreads();

    if (tid == 0) {
        float mx = s_val[0];
        float sum = 0.f;
        for (int k2 = 0; k2 < TOPK; k2++) {
            float e = ref_exp(s_val[k2] - mx);
            s_val[k2] = e;
            sum += e;
        }
        for (int k2 = 0; k2 < TOPK; k2++) s_val[k2] = __fdiv_rn(s_val[k2], sum);
    }
    __syncthreads();

    const float* vb = memv + (size_t)a * Nz * Dz;
    float a0 = 0.f, a1 = 0.f;
    int d0 = tid, d1 = tid + 256;
    for (int k2 = 0; k2 < TOPK; k2++) {
        const float* vr = vb + (size_t)s_idx[k2] * Dz;
        float w2 = s_val[k2];
        a0 = fmaf(w2, vr[d0], a0);
        a1 = fmaf(w2, vr[d1], a1);
    }
    s_cur[d0] = a0;
    s_cur[d1] = a1;
    g_cur[b * Dz + d0] = a0;
    g_cur[b * Dz + d1] = a1;
    __syncthreads();

    if (tid < 8) {
        float acc = 0.f;
        for (int i = 0; i < Dz / 8; i++) {
            float x = s_cur[8 * i + tid];
            acc = fmaf(x, x, acc);
        }
        s_acc8[tid] = acc;
    }
    __syncthreads();
    if (tid == 0) {
        float e0 = s_acc8[0] + s_acc8[4], e1 = s_acc8[1] + s_acc8[5];
        float e2 = s_acc8[2] + s_acc8[6], e3 = s_acc8[3] + s_acc8[7];
        float f0 = e0 + e2, f1 = e1 + e3;
        sh_denom = __fsqrt_rn(f0 + f1) + 1e-8f;
    }
    __syncthreads();
    float dn = sh_denom;
    float q0 = __fdiv_rn(a0, dn);
    float q1 = __fdiv_rn(a1, dn);
    g_qn[b * Dz + d0] = q0;
    g_qn[b * Dz + d1] = q1;
    g_qh[b * Dz + d0] = __float2half_rn(q0);
    g_qh[b * Dz + d1] = __float2half_rn(q1);
}

// ---------------- fused 3-layer MLP (512->256->128->1, elu) ----------------
__global__ __launch_bounds__(256) void mlp_kernel(const float* __restrict__ emb, int use_emb,
                                                  const float* __restrict__ W1, const float* __restrict__ b1,
                                                  const float* __restrict__ W2, const float* __restrict__ b2,
                                                  const float* __restrict__ W3, const float* __restrict__ b3,
                                                  float* __restrict__ out, int off, int stride) {
    __shared__ float Xs[8 * 512];
    __shared__ float H1[8 * 256];
    __shared__ float H2[8 * 128];
    const float* X = use_emb ? emb : g_cur;
    int tid = threadIdx.x;
    int b0 = blockIdx.x * 8;

    for (int i = tid; i < 8 * 512; i += 256) Xs[i] = X[(size_t)b0 * 512 + i];
    __syncthreads();
    {
        int j = tid;
        float acc[8];
#pragma unroll
        for (int bb = 0; bb < 8; bb++) acc[bb] = 0.f;
        for (int d = 0; d < 512; d += 4) {
            float w0 = W1[(d + 0) * 256 + j];
            float w1 = W1[(d + 1) * 256 + j];
            float w2v = W1[(d + 2) * 256 + j];
            float w3v = W1[(d + 3) * 256 + j];
#pragma unroll
            for (int bb = 0; bb < 8; bb++) {
                float4 x = *(const float4*)(&Xs[bb * 512 + d]);
                acc[bb] = fmaf(x.x, w0, acc[bb]);
                acc[bb] = fmaf(x.y, w1, acc[bb]);
                acc[bb] = fmaf(x.z, w2v, acc[bb]);
                acc[bb] = fmaf(x.w, w3v, acc[bb]);
            }
        }
        float bj = b1[j];
#pragma unroll
        for (int bb = 0; bb < 8; bb++) {
            float h = acc[bb] + bj;
            H1[bb * 256 + j] = (h > 0.f) ? h : expm1f(h);
        }
    }
    __syncthreads();
    {
        int j2 = tid & 127, g = tid >> 7;
        float acc[4] = {0.f, 0.f, 0.f, 0.f};
        for (int j = 0; j < 256; j++) {
            float w = W2[j * 128 + j2];
#pragma unroll
            for (int ii = 0; ii < 4; ii++) acc[ii] = fmaf(H1[(g * 4 + ii) * 256 + j], w, acc[ii]);
        }
        float bj = b2[j2];
#pragma unroll
        for (int ii = 0; ii < 4; ii++) {
            float h = acc[ii] + bj;
            H2[(g * 4 + ii) * 128 + j2] = (h > 0.f) ? h : expm1f(h);
        }
    }
    __syncthreads();
    {
        int wid = tid >> 5, lane = tid & 31;
        float s = 0.f;
        for (int j = lane; j < 128; j += 32) s = fmaf(H2[wid * 128 + j], W3[j], s);
        s = warp_sum(s);
        if (lane == 0) out[off + (size_t)(b0 + wid) * stride] = s + b3[0];
    }
}

// ---------------- orchestration ----------------
extern "C" void kernel_launch(void* const* d_in, const int* in_sizes, int n_in,
                              void* d_out, int out_size) {
    const float* emb     = (const float*)d_in[0];
    const float* keys    = (const float*)d_in[1];
    const float* memv    = (const float*)d_in[2];
    const float* W1      = (const float*)d_in[3];
    const float* b1      = (const float*)d_in[4];
    const float* W2      = (const float*)d_in[5];
    const float* b2      = (const float*)d_in[6];
    const float* W3      = (const float*)d_in[7];
    const float* b3      = (const float*)d_in[8];
    const int*   actions = (const int*)d_in[9];
    float* out = (float*)d_out;

    cudaFuncSetAttribute(sims_mma, cudaFuncAttributeMaxDynamicSharedMemorySize, SIMS_DYN_SMEM);

    row_denom_kernel<<<(Az * Nz + 255) / 256, 256>>>(keys, 0, Az * Nz);
    normalize_kernel<<<2048, 256>>>(keys, 0, (Az * Nz * Dz) / 4);
    row_denom_kernel<<<(Bsz + 255) / 256, 256>>>(emb, 1, Bsz);
    normalize_kernel<<<512, 256>>>(emb, 1, (Bsz * Dz) / 4);
    group_kernel<<<1, 256>>>(actions);

    mlp_kernel<<<Bsz / 8, 256>>>(emb, 1, W1, b1, W2, b2, W3, b3, out, 0, 1);

    for (int t = 0; t < NSTEP; t++) {
        sims_mma<<<dim3(Nz / 128, MT), 256, SIMS_DYN_SMEM>>>(t);
        topk_kernel<<<Bsz, 256>>>(memv, actions, t);
        mlp_kernel<<<Bsz / 8, 256>>>(emb, 0, W1, b1, W2, b2, W3, b3, out, Bsz + t, 5);
    }
}

// round 13
// speedup vs baseline: 2.9178x; 1.0005x over previous
#include <cuda_runtime.h>
#include <cuda_fp16.h>
#include <cstdint>
#include <math.h>

#define Bsz   1024
#define Az    5
#define Nz    16384
#define Dz    512
#define TOPK  50
#define NSTEP 5
#define MT    13          // max padded 128-row tiles
#define CAND_CAP 1024
#define MARGIN 0.006f
#define SIMS_DYN_SMEM (4 * 16384 + 1024)

// ---- scratch (device globals, no allocations) ----
__device__ float  g_kn[(size_t)Az * Nz * Dz];     // fp32 normalized keys (exact path)
__device__ __half g_kh[(size_t)Az * Nz * Dz];     // fp16 normalized keys (MMA path)
__device__ float  g_qn[Bsz * Dz];
__device__ __half g_qh[Bsz * Dz];
__device__ float  g_cur[Bsz * Dz];
__device__ __half g_simh[(size_t)Bsz * Nz];       // 32 MB approx sims
__device__ unsigned g_bmaxkey[Bsz * 128];         // per (row, 128-col block) max (sortable u16 key)
__device__ float  g_kdenom[Az * Nz];
__device__ float  g_qdenom[Bsz];
__device__ int    g_row_map[NSTEP][MT * 128];
__device__ int    g_tile_action[NSTEP][MT];

__device__ __forceinline__ uint32_t smem_u32(const void* p) {
    uint32_t a;
    asm("{ .reg .u64 t; cvta.to.shared.u64 t, %1; cvt.u32.u64 %0, t; }" : "=r"(a) : "l"(p));
    return a;
}

#define SMEM_SWZ(off) ((off) ^ (((off) >> 3) & 0x70))

__device__ __forceinline__ void cp_async16(uint32_t dst, const void* src, bool valid) {
    int sz = valid ? 16 : 0;
    asm volatile("cp.async.cg.shared.global [%0], [%1], 16, %2;"
                 :: "r"(dst), "l"(src), "r"(sz) : "memory");
}
#define CP_COMMIT() asm volatile("cp.async.commit_group;" ::: "memory")
#define CP_WAIT(n)  asm volatile("cp.async.wait_group %0;" :: "n"(n) : "memory")

__device__ __forceinline__ void ldmatrix_x4(uint32_t* r, uint32_t addr) {
    asm volatile("ldmatrix.sync.aligned.m8n8.x4.shared.b16 {%0,%1,%2,%3}, [%4];"
                 : "=r"(r[0]), "=r"(r[1]), "=r"(r[2]), "=r"(r[3]) : "r"(addr));
}
__device__ __forceinline__ void mma_16816(float* c, const uint32_t* a, uint32_t b0, uint32_t b1) {
    asm volatile(
        "mma.sync.aligned.m16n8k16.row.col.f32.f16.f16.f32 "
        "{%0,%1,%2,%3}, {%4,%5,%6,%7}, {%8,%9}, {%0,%1,%2,%3};"
        : "+f"(c[0]), "+f"(c[1]), "+f"(c[2]), "+f"(c[3])
        : "r"(a[0]), "r"(a[1]), "r"(a[2]), "r"(a[3]), "r"(b0), "r"(b1));
}

__device__ __forceinline__ float warp_sum(float v) {
#pragma unroll
    for (int o = 16; o; o >>= 1) v += __shfl_xor_sync(0xffffffffu, v, o);
    return v;
}

// Cephes/Eigen-style expf — numerics frozen from passing round
__device__ __forceinline__ float ref_exp(float x) {
    float m = floorf(fmaf(x, 1.44269504088896341f, 0.5f));
    float r = fmaf(m, -0.693359375f, x);
    r = fmaf(m, 2.12194440e-4f, r);
    float r2 = r * r;
    float p = 1.9875691500E-4f;
    p = fmaf(p, r, 1.3981999507E-3f);
    p = fmaf(p, r, 8.3334519073E-3f);
    p = fmaf(p, r, 4.1665795894E-2f);
    p = fmaf(p, r, 1.6666665459E-1f);
    p = fmaf(p, r, 5.0000001201E-1f);
    float y = fmaf(p, r2, r) + 1.0f;
    return ldexpf(y, (int)m);
}

__device__ __forceinline__ unsigned hsort16(unsigned h) {
    return (h & 0x8000u) ? (0xFFFFu & ~h) : (h | 0x8000u);
}
__device__ __forceinline__ float hkey2float(unsigned k) {
    unsigned hb = (k & 0x8000u) ? (k ^ 0x8000u) : (0xFFFFu & ~k);
    return __half2float(__ushort_as_half((unsigned short)hb));
}

// ---------------- row denominators ----------------
__global__ void row_denom_kernel(const float* __restrict__ X, int which, int nrows) {
    int r = blockIdx.x * blockDim.x + threadIdx.x;
    if (r >= nrows) return;
    const float4* p = (const float4*)(X + (size_t)r * Dz);
    float a[8];
#pragma unroll
    for (int j = 0; j < 8; j++) a[j] = 0.f;
    for (int i = 0; i < Dz / 8; i++) {
        float4 v0 = p[2 * i];
        float4 v1 = p[2 * i + 1];
        a[0] = fmaf(v0.x, v0.x, a[0]); a[1] = fmaf(v0.y, v0.y, a[1]);
        a[2] = fmaf(v0.z, v0.z, a[2]); a[3] = fmaf(v0.w, v0.w, a[3]);
        a[4] = fmaf(v1.x, v1.x, a[4]); a[5] = fmaf(v1.y, v1.y, a[5]);
        a[6] = fmaf(v1.z, v1.z, a[6]); a[7] = fmaf(v1.w, v1.w, a[7]);
    }
    float e0 = a[0] + a[4], e1 = a[1] + a[5], e2 = a[2] + a[6], e3 = a[3] + a[7];
    float f0 = e0 + e2, f1 = e1 + e3;
    float d = __fsqrt_rn(f0 + f1) + 1e-8f;
    if (which) g_qdenom[r] = d; else g_kdenom[r] = d;
}

// ---------------- normalize (IEEE div) + fp16 pack ----------------
__global__ void normalize_kernel(const float* __restrict__ X, int which, int n4) {
    float* Y = which ? g_qn : g_kn;
    __half* Yh = which ? g_qh : g_kh;
    const float* D = which ? g_qdenom : g_kdenom;
    for (int i = blockIdx.x * blockDim.x + threadIdx.x; i < n4; i += gridDim.x * blockDim.x) {
        float4 v = ((const float4*)X)[i];
        float d = D[i >> 7];
        float4 o;
        o.x = __fdiv_rn(v.x, d); o.y = __fdiv_rn(v.y, d);
        o.z = __fdiv_rn(v.z, d); o.w = __fdiv_rn(v.w, d);
        ((float4*)Y)[i] = o;
        __half2 h0 = __float22half2_rn(make_float2(o.x, o.y));
        __half2 h1 = __float22half2_rn(make_float2(o.z, o.w));
        uint2 pk;
        pk.x = *reinterpret_cast<unsigned*>(&h0);
        pk.y = *reinterpret_cast<unsigned*>(&h1);
        ((uint2*)Yh)[i] = pk;
    }
}

// ---------------- group batches by selected action ----------------
__global__ void group_kernel(const int* __restrict__ actions) {
    __shared__ int cnt[Az], cur[Az];
    int tid = threadIdx.x;
    for (int t = 0; t < NSTEP; t++) {
        if (tid < Az) cnt[tid] = 0;
        __syncthreads();
        for (int b = tid; b < Bsz; b += blockDim.x)
            atomicAdd(&cnt[actions[b * NSTEP + t]], 1);
        __syncthreads();
        if (tid == 0) {
            int off = 0;
            for (int a = 0; a < Az; a++) {
                cur[a] = off;
                off += ((cnt[a] + 127) >> 7) << 7;
            }
        }
        __syncthreads();
        for (int i = tid; i < MT * 128; i += blockDim.x) g_row_map[t][i] = -1;
        __syncthreads();
        for (int b = tid; b < Bsz; b += blockDim.x) {
            int a = actions[b * NSTEP + t];
            int p = atomicAdd(&cur[a], 1);
            g_row_map[t][p] = b;
        }
        if (tid < MT) {
            int mt = tid, act = -1, off = 0;
            for (int a = 0; a < Az; a++) {
                int len = ((cnt[a] + 127) >> 7) << 7;
                if (mt * 128 >= off && mt * 128 < off + len) act = a;
                off += len;
            }
            g_tile_action[t][mt] = act;
        }
        __syncthreads();
    }
}

// ---------------- HMMA fp16 approx GEMM + per-block row maxes ----------------
__global__ __launch_bounds__(256, 2) void sims_mma(int t) {
    extern __shared__ unsigned char dyn_smem[];
    __shared__ int rs[128];
    __shared__ unsigned s_rmax[2][128];

    int mt = blockIdx.y;
    int act = g_tile_action[t][mt];
    if (act < 0) return;
    int n0 = blockIdx.x * 128;

    int tid = threadIdx.x, wid = tid >> 5, lane = tid & 31;
    if (tid < 128) rs[tid] = g_row_map[t][mt * 128 + tid];
    __syncthreads();

    unsigned char* base = (unsigned char*)(((uintptr_t)dyn_smem + 1023) & ~(uintptr_t)1023);
    uint32_t sAu[2] = { smem_u32(base),         smem_u32(base + 16384) };
    uint32_t sBu[2] = { smem_u32(base + 32768), smem_u32(base + 49152) };

    int warp_m = wid >> 1, warp_n = wid & 1;
    int m_base = warp_m * 32, nb_base = warp_n * 64;

    const uint4* qb = (const uint4*)g_qh;
    const uint4* kb = (const uint4*)(g_kh + ((size_t)act * Nz + n0) * Dz);

    float c[2][8][4];
#pragma unroll
    for (int i = 0; i < 2; i++)
#pragma unroll
        for (int j = 0; j < 8; j++)
#pragma unroll
            for (int k = 0; k < 4; k++) c[i][j][k] = 0.f;

    int lrow = lane & 15, lslot = lane >> 4;

    int srow_[4], si4_[4], sar_[4];
    unsigned sw_[4];
#pragma unroll
    for (int rep = 0; rep < 4; rep++) {
        int idx = tid + rep * 256;
        srow_[rep] = idx >> 3;
        si4_[rep] = idx & 7;
        sar_[rep] = rs[srow_[rep]];
        sw_[rep] = SMEM_SWZ(srow_[rep] * 128 + si4_[rep] * 16);
    }

    auto stage = [&](int kc, int buf) {
#pragma unroll
        for (int rep = 0; rep < 4; rep++) {
            int ar = sar_[rep];
            cp_async16(sAu[buf] + sw_[rep],
                       qb + (size_t)(ar < 0 ? 0 : ar) * 64 + kc * 8 + si4_[rep], ar >= 0);
            cp_async16(sBu[buf] + sw_[rep],
                       kb + (size_t)srow_[rep] * 64 + kc * 8 + si4_[rep], true);
        }
        CP_COMMIT();
    };

    stage(0, 0);
#pragma unroll 1
    for (int kc = 0; kc < 8; kc++) {
        int buf = kc & 1;
        if (kc + 1 < 8) { stage(kc + 1, buf ^ 1); CP_WAIT(1); }
        else            { CP_WAIT(0); }
        __syncthreads();
#pragma unroll
        for (int k16 = 0; k16 < 4; k16++) {
            int slot16 = (2 * k16 + lslot) * 16;
            uint32_t a[2][4];
#pragma unroll
            for (int mi = 0; mi < 2; mi++) {
                int row = m_base + mi * 16 + lrow;
                ldmatrix_x4(a[mi], sAu[buf] + row * 128 + (slot16 ^ ((row & 7) << 4)));
            }
            uint32_t bf[4][4];
#pragma unroll
            for (int nb = 0; nb < 4; nb++) {
                int row = nb_base + nb * 16 + lrow;
                ldmatrix_x4(bf[nb], sBu[buf] + row * 128 + (slot16 ^ ((row & 7) << 4)));
            }
#pragma unroll
            for (int mi = 0; mi < 2; mi++)
#pragma unroll
                for (int nj = 0; nj < 8; nj++) {
                    int nb = nj >> 1, hi = nj & 1;
                    mma_16816(c[mi][nj], a[mi], bf[nb][hi], bf[nb][hi + 2]);
                }
        }
        __syncthreads();
    }

    // epilogue: store half sims + per-row block-max keys
    unsigned km[2][2];
    km[0][0] = km[0][1] = km[1][0] = km[1][1] = 0u;
#pragma unroll
    for (int mi = 0; mi < 2; mi++) {
        int r0 = rs[m_base + mi * 16 + (lane >> 2)];
        int r1 = rs[m_base + mi * 16 + (lane >> 2) + 8];
#pragma unroll
        for (int nj = 0; nj < 8; nj++) {
            int col = n0 + nb_base + nj * 8 + (lane & 3) * 2;
            __half2 h0 = __floats2half2_rn(c[mi][nj][0], c[mi][nj][1]);
            __half2 h1 = __floats2half2_rn(c[mi][nj][2], c[mi][nj][3]);
            unsigned u0 = *reinterpret_cast<unsigned*>(&h0);
            unsigned u1 = *reinterpret_cast<unsigned*>(&h1);
            km[mi][0] = max(km[mi][0], max(hsort16(u0 & 0xFFFFu), hsort16(u0 >> 16)));
            km[mi][1] = max(km[mi][1], max(hsort16(u1 & 0xFFFFu), hsort16(u1 >> 16)));
            if (r0 >= 0) *(unsigned*)(g_simh + (size_t)r0 * Nz + col) = u0;
            if (r1 >= 0) *(unsigned*)(g_simh + (size_t)r1 * Nz + col) = u1;
        }
    }
#pragma unroll
    for (int mi = 0; mi < 2; mi++)
#pragma unroll
        for (int rr = 0; rr < 2; rr++) {
            unsigned v = km[mi][rr];
            v = max(v, __shfl_xor_sync(0xffffffffu, v, 1));
            v = max(v, __shfl_xor_sync(0xffffffffu, v, 2));
            if ((lane & 3) == 0)
                s_rmax[warp_n][m_base + mi * 16 + (lane >> 2) + rr * 8] = v;
        }
    __syncthreads();
    if (tid < 128) {
        int r = rs[tid];
        if (r >= 0)
            g_bmaxkey[r * 128 + blockIdx.x] = max(s_rmax[0][tid], s_rmax[1][tid]);
    }
}

// ---------------- topk: block-max threshold -> 1 scan -> a50 refine -> exact rescoring ----------------
__global__ __launch_bounds__(256) void topk_kernel(const float* __restrict__ memv,
                                                   const int* __restrict__ actions, int t) {
    __shared__ unsigned s_bk[128];
    __shared__ unsigned char s_skip[128];
    __shared__ unsigned sh_T0, sh_a50;
    __shared__ float4 s_q4[Dz / 4];
    __shared__ int   s_cidx[CAND_CAP];
    __shared__ float s_cvala[CAND_CAP];   // approx values
    __shared__ float s_cval[CAND_CAP];    // exact values (or -inf)
    __shared__ int   s_cnt;
    __shared__ float s_val[TOPK];
    __shared__ int   s_idx[TOPK];
    __shared__ float s_cur[Dz];
    __shared__ float s_acc8[8];
    __shared__ float sh_denom;

    int b = blockIdx.x;
    int tid = threadIdx.x;
    const uint4* srow8 = (const uint4*)(g_simh + (size_t)b * Nz);

    if (tid == 0) { s_cnt = 0; sh_T0 = 0xFFFFFFFFu; sh_a50 = 0xFFFFFFFFu; }
    if (tid < 128) s_bk[tid] = g_bmaxkey[b * 128 + tid];
    for (int i = tid; i < Dz; i += 256)
        ((float*)s_q4)[i] = g_qn[(size_t)b * Dz + i];
    __syncthreads();

    // 50th-largest block max (M50 <= row's rank-50 value)
    if (tid < 128) {
        unsigned v = s_bk[tid];
        int cg = 0;
        for (int j = 0; j < 128; j++) cg += (s_bk[j] > v);
        if (cg <= 49) atomicMin(&sh_T0, v);
    }
    __syncthreads();
    float Tf = hkey2float(sh_T0) - MARGIN;
    if (tid < 128) s_skip[tid] = (hkey2float(s_bk[tid]) < Tf) ? 1 : 0;
    __syncthreads();

    // single candidate scan with block skipping
    for (int i8 = tid; i8 < Nz / 8; i8 += 256) {
        if (s_skip[i8 >> 4]) continue;
        uint4 v = srow8[i8];
        unsigned w[4] = {v.x, v.y, v.z, v.w};
#pragma unroll
        for (int c2 = 0; c2 < 4; c2++) {
            float2 f = __half22float2(*reinterpret_cast<__half2*>(&w[c2]));
            if (f.x >= Tf) {
                int p = atomicAdd(&s_cnt, 1);
                if (p < CAND_CAP) { s_cidx[p] = i8 * 8 + c2 * 2; s_cvala[p] = f.x; }
            }
            if (f.y >= Tf) {
                int p = atomicAdd(&s_cnt, 1);
                if (p < CAND_CAP) { s_cidx[p] = i8 * 8 + c2 * 2 + 1; s_cvala[p] = f.y; }
            }
        }
    }
    __syncthreads();
    int C = min(s_cnt, CAND_CAP);

    // a50 = 50th-largest approx value among candidates (== global approx rank-50)
    for (int c = tid; c < C; c += 256) {
        float v = s_cvala[c];
        int cg = 0;
        for (int j = 0; j < C; j++) cg += (s_cvala[j] > v);
        if (cg <= 49) {
            unsigned u = __float_as_uint(v);
            u = (u & 0x80000000u) ? ~u : (u | 0x80000000u);
            atomicMin(&sh_a50, u);
        }
    }
    __syncthreads();
    unsigned ua = sh_a50;
    ua = (ua & 0x80000000u) ? (ua ^ 0x80000000u) : ~ua;
    float ft = __uint_as_float(ua) - MARGIN;

    // exact fp32 rescoring of the refined set (d-ascending fmaf chain, frozen numerics)
    int a = actions[b * NSTEP + t];
    const float* knb = g_kn + (size_t)a * Nz * Dz;
    for (int c = tid; c < C; c += 256) {
        if (s_cvala[c] < ft) { s_cval[c] = -3.4e38f; continue; }
        const float4* kr = (const float4*)(knb + (size_t)s_cidx[c] * Dz);
        float acc = 0.f;
#pragma unroll 4
        for (int d4 = 0; d4 < Dz / 4; d4++) {
            float4 kv = __ldg(&kr[d4]);
            float4 qv = s_q4[d4];
            acc = fmaf(qv.x, kv.x, acc);
            acc = fmaf(qv.y, kv.y, acc);
            acc = fmaf(qv.z, kv.z, acc);
            acc = fmaf(qv.w, kv.w, acc);
        }
        s_cval[c] = acc;
    }
    __syncthreads();

    // exact ranking (value desc, index asc) into slots 0..49
    for (int c = tid; c < C; c += 256) {
        float v = s_cval[c];
        int id = s_cidx[c];
        int rank = 0;
        for (int j = 0; j < C; j++) {
            float vj = s_cval[j];
            rank += (vj > v) || (vj == v && s_cidx[j] < id);
        }
        if (rank < TOPK) { s_val[rank] = v; s_idx[rank] = id; }
    }
    __syncthreads();

    if (tid == 0) {
        float mx = s_val[0];
        float sum = 0.f;
        for (int k2 = 0; k2 < TOPK; k2++) {
            float e = ref_exp(s_val[k2] - mx);
            s_val[k2] = e;
            sum += e;
        }
        for (int k2 = 0; k2 < TOPK; k2++) s_val[k2] = __fdiv_rn(s_val[k2], sum);
    }
    __syncthreads();

    const float* vb = memv + (size_t)a * Nz * Dz;
    float a0 = 0.f, a1 = 0.f;
    int d0 = tid, d1 = tid + 256;
    for (int k2 = 0; k2 < TOPK; k2++) {
        const float* vr = vb + (size_t)s_idx[k2] * Dz;
        float w2 = s_val[k2];
        a0 = fmaf(w2, vr[d0], a0);
        a1 = fmaf(w2, vr[d1], a1);
    }
    s_cur[d0] = a0;
    s_cur[d1] = a1;
    g_cur[b * Dz + d0] = a0;
    g_cur[b * Dz + d1] = a1;
    __syncthreads();

    if (tid < 8) {
        float acc = 0.f;
        for (int i = 0; i < Dz / 8; i++) {
            float x = s_cur[8 * i + tid];
            acc = fmaf(x, x, acc);
        }
        s_acc8[tid] = acc;
    }
    __syncthreads();
    if (tid == 0) {
        float e0 = s_acc8[0] + s_acc8[4], e1 = s_acc8[1] + s_acc8[5];
        float e2 = s_acc8[2] + s_acc8[6], e3 = s_acc8[3] + s_acc8[7];
        float f0 = e0 + e2, f1 = e1 + e3;
        sh_denom = __fsqrt_rn(f0 + f1) + 1e-8f;
    }
    __syncthreads();
    float dn = sh_denom;
    float q0 = __fdiv_rn(a0, dn);
    float q1 = __fdiv_rn(a1, dn);
    g_qn[b * Dz + d0] = q0;
    g_qn[b * Dz + d1] = q1;
    g_qh[b * Dz + d0] = __float2half_rn(q0);
    g_qh[b * Dz + d1] = __float2half_rn(q1);
}

// ---------------- fused 3-layer MLP (512->256->128->1, elu) ----------------
__global__ __launch_bounds__(256) void mlp_kernel(const float* __restrict__ emb, int use_emb,
                                                  const float* __restrict__ W1, const float* __restrict__ b1,
                                                  const float* __restrict__ W2, const float* __restrict__ b2,
                                                  const float* __restrict__ W3, const float* __restrict__ b3,
                                                  float* __restrict__ out, int off, int stride) {
    __shared__ float Xs[8 * 512];
    __shared__ float H1[8 * 256];
    __shared__ float H2[8 * 128];
    const float* X = use_emb ? emb : g_cur;
    int tid = threadIdx.x;
    int b0 = blockIdx.x * 8;

    for (int i = tid; i < 8 * 512; i += 256) Xs[i] = X[(size_t)b0 * 512 + i];
    __syncthreads();
    {
        int j = tid;
        float acc[8];
#pragma unroll
        for (int bb = 0; bb < 8; bb++) acc[bb] = 0.f;
        for (int d = 0; d < 512; d += 4) {
            float w0 = W1[(d + 0) * 256 + j];
            float w1 = W1[(d + 1) * 256 + j];
            float w2v = W1[(d + 2) * 256 + j];
            float w3v = W1[(d + 3) * 256 + j];
#pragma unroll
            for (int bb = 0; bb < 8; bb++) {
                float4 x = *(const float4*)(&Xs[bb * 512 + d]);
                acc[bb] = fmaf(x.x, w0, acc[bb]);
                acc[bb] = fmaf(x.y, w1, acc[bb]);
                acc[bb] = fmaf(x.z, w2v, acc[bb]);
                acc[bb] = fmaf(x.w, w3v, acc[bb]);
            }
        }
        float bj = b1[j];
#pragma unroll
        for (int bb = 0; bb < 8; bb++) {
            float h = acc[bb] + bj;
            H1[bb * 256 + j] = (h > 0.f) ? h : expm1f(h);
        }
    }
    __syncthreads();
    {
        int j2 = tid & 127, g = tid >> 7;
        float acc[4] = {0.f, 0.f, 0.f, 0.f};
        for (int j = 0; j < 256; j++) {
            float w = W2[j * 128 + j2];
#pragma unroll
            for (int ii = 0; ii < 4; ii++) acc[ii] = fmaf(H1[(g * 4 + ii) * 256 + j], w, acc[ii]);
        }
        float bj = b2[j2];
#pragma unroll
        for (int ii = 0; ii < 4; ii++) {
            float h = acc[ii] + bj;
            H2[(g * 4 + ii) * 128 + j2] = (h > 0.f) ? h : expm1f(h);
        }
    }
    __syncthreads();
    {
        int wid = tid >> 5, lane = tid & 31;
        float s = 0.f;
        for (int j = lane; j < 128; j += 32) s = fmaf(H2[wid * 128 + j], W3[j], s);
        s = warp_sum(s);
        if (lane == 0) out[off + (size_t)(b0 + wid) * stride] = s + b3[0];
    }
}

// ---------------- orchestration ----------------
extern "C" void kernel_launch(void* const* d_in, const int* in_sizes, int n_in,
                              void* d_out, int out_size) {
    const float* emb     = (const float*)d_in[0];
    const float* keys    = (const float*)d_in[1];
    const float* memv    = (const float*)d_in[2];
    const float* W1      = (const float*)d_in[3];
    const float* b1      = (const float*)d_in[4];
    const float* W2      = (const float*)d_in[5];
    const float* b2      = (const float*)d_in[6];
    const float* W3      = (const float*)d_in[7];
    const float* b3      = (const float*)d_in[8];
    const int*   actions = (const int*)d_in[9];
    float* out = (float*)d_out;

    cudaFuncSetAttribute(sims_mma, cudaFuncAttributeMaxDynamicSharedMemorySize, SIMS_DYN_SMEM);

    row_denom_kernel<<<(Az * Nz + 255) / 256, 256>>>(keys, 0, Az * Nz);
    normalize_kernel<<<2048, 256>>>(keys, 0, (Az * Nz * Dz) / 4);
    row_denom_kernel<<<(Bsz + 255) / 256, 256>>>(emb, 1, Bsz);
    normalize_kernel<<<512, 256>>>(emb, 1, (Bsz * Dz) / 4);
    group_kernel<<<1, 256>>>(actions);

    mlp_kernel<<<Bsz / 8, 256>>>(emb, 1, W1, b1, W2, b2, W3, b3, out, 0, 1);

    for (int t = 0; t < NSTEP; t++) {
        sims_mma<<<dim3(Nz / 128, MT), 256, SIMS_DYN_SMEM>>>(t);
        topk_kernel<<<Bsz, 256>>>(memv, actions, t);
        mlp_kernel<<<Bsz / 8, 256>>>(emb, 0, W1, b1, W2, b2, W3, b3, out, Bsz + t, 5);
    }
}

// round 14
// speedup vs baseline: 2.9202x; 1.0008x over previous
#include <cuda_runtime.h>
#include <cuda_fp16.h>
#include <cstdint>
#include <math.h>

#define Bsz   1024
#define Az    5
#define Nz    16384
#define Dz    512
#define TOPK  50
#define NSTEP 5
#define MT    13          // max padded 128-row tiles
#define CAND_CAP 1024
#define MARGIN 0.006f
#define SIMS_DYN_SMEM (4 * 16384 + 1024)

// ---- scratch (device globals, no allocations) ----
__device__ float  g_kn[(size_t)Az * Nz * Dz];     // fp32 normalized keys (exact path)
__device__ __half g_kh[(size_t)Az * Nz * Dz];     // fp16 normalized keys (MMA path)
__device__ float  g_qn[Bsz * Dz];
__device__ __half g_qh[Bsz * Dz];
__device__ float  g_cur[Bsz * Dz];
__device__ __half g_simh[(size_t)Bsz * Nz];       // 32 MB approx sims
__device__ unsigned g_bmaxkey[Bsz * 128];         // per (row, 128-col block) max (sortable u16 key)
__device__ float  g_kdenom[Az * Nz];
__device__ float  g_qdenom[Bsz];
__device__ int    g_row_map[NSTEP][MT * 128];
__device__ int    g_tile_action[NSTEP][MT];

__device__ __forceinline__ uint32_t smem_u32(const void* p) {
    uint32_t a;
    asm("{ .reg .u64 t; cvta.to.shared.u64 t, %1; cvt.u32.u64 %0, t; }" : "=r"(a) : "l"(p));
    return a;
}

#define SMEM_SWZ(off) ((off) ^ (((off) >> 3) & 0x70))

__device__ __forceinline__ void cp_async16(uint32_t dst, const void* src, bool valid) {
    int sz = valid ? 16 : 0;
    asm volatile("cp.async.cg.shared.global [%0], [%1], 16, %2;"
                 :: "r"(dst), "l"(src), "r"(sz) : "memory");
}
#define CP_COMMIT() asm volatile("cp.async.commit_group;" ::: "memory")
#define CP_WAIT(n)  asm volatile("cp.async.wait_group %0;" :: "n"(n) : "memory")

__device__ __forceinline__ void ldmatrix_x4(uint32_t* r, uint32_t addr) {
    asm volatile("ldmatrix.sync.aligned.m8n8.x4.shared.b16 {%0,%1,%2,%3}, [%4];"
                 : "=r"(r[0]), "=r"(r[1]), "=r"(r[2]), "=r"(r[3]) : "r"(addr));
}
__device__ __forceinline__ void mma_16816(float* c, const uint32_t* a, uint32_t b0, uint32_t b1) {
    asm volatile(
        "mma.sync.aligned.m16n8k16.row.col.f32.f16.f16.f32 "
        "{%0,%1,%2,%3}, {%4,%5,%6,%7}, {%8,%9}, {%0,%1,%2,%3};"
        : "+f"(c[0]), "+f"(c[1]), "+f"(c[2]), "+f"(c[3])
        : "r"(a[0]), "r"(a[1]), "r"(a[2]), "r"(a[3]), "r"(b0), "r"(b1));
}

__device__ __forceinline__ float warp_sum(float v) {
#pragma unroll
    for (int o = 16; o; o >>= 1) v += __shfl_xor_sync(0xffffffffu, v, o);
    return v;
}

// Cephes/Eigen-style expf — numerics frozen from passing round
__device__ __forceinline__ float ref_exp(float x) {
    float m = floorf(fmaf(x, 1.44269504088896341f, 0.5f));
    float r = fmaf(m, -0.693359375f, x);
    r = fmaf(m, 2.12194440e-4f, r);
    float r2 = r * r;
    float p = 1.9875691500E-4f;
    p = fmaf(p, r, 1.3981999507E-3f);
    p = fmaf(p, r, 8.3334519073E-3f);
    p = fmaf(p, r, 4.1665795894E-2f);
    p = fmaf(p, r, 1.6666665459E-1f);
    p = fmaf(p, r, 5.0000001201E-1f);
    float y = fmaf(p, r2, r) + 1.0f;
    return ldexpf(y, (int)m);
}

__device__ __forceinline__ unsigned hsort16(unsigned h) {
    return (h & 0x8000u) ? (0xFFFFu & ~h) : (h | 0x8000u);
}
__device__ __forceinline__ float hkey2float(unsigned k) {
    unsigned hb = (k & 0x8000u) ? (k ^ 0x8000u) : (0xFFFFu & ~k);
    return __half2float(__ushort_as_half((unsigned short)hb));
}

// ---------------- row denominators ----------------
__global__ void row_denom_kernel(const float* __restrict__ X, int which, int nrows) {
    int r = blockIdx.x * blockDim.x + threadIdx.x;
    if (r >= nrows) return;
    const float4* p = (const float4*)(X + (size_t)r * Dz);
    float a[8];
#pragma unroll
    for (int j = 0; j < 8; j++) a[j] = 0.f;
    for (int i = 0; i < Dz / 8; i++) {
        float4 v0 = p[2 * i];
        float4 v1 = p[2 * i + 1];
        a[0] = fmaf(v0.x, v0.x, a[0]); a[1] = fmaf(v0.y, v0.y, a[1]);
        a[2] = fmaf(v0.z, v0.z, a[2]); a[3] = fmaf(v0.w, v0.w, a[3]);
        a[4] = fmaf(v1.x, v1.x, a[4]); a[5] = fmaf(v1.y, v1.y, a[5]);
        a[6] = fmaf(v1.z, v1.z, a[6]); a[7] = fmaf(v1.w, v1.w, a[7]);
    }
    float e0 = a[0] + a[4], e1 = a[1] + a[5], e2 = a[2] + a[6], e3 = a[3] + a[7];
    float f0 = e0 + e2, f1 = e1 + e3;
    float d = __fsqrt_rn(f0 + f1) + 1e-8f;
    if (which) g_qdenom[r] = d; else g_kdenom[r] = d;
}

// ---------------- normalize (IEEE div) + fp16 pack ----------------
__global__ void normalize_kernel(const float* __restrict__ X, int which, int n4) {
    float* Y = which ? g_qn : g_kn;
    __half* Yh = which ? g_qh : g_kh;
    const float* D = which ? g_qdenom : g_kdenom;
    for (int i = blockIdx.x * blockDim.x + threadIdx.x; i < n4; i += gridDim.x * blockDim.x) {
        float4 v = ((const float4*)X)[i];
        float d = D[i >> 7];
        float4 o;
        o.x = __fdiv_rn(v.x, d); o.y = __fdiv_rn(v.y, d);
        o.z = __fdiv_rn(v.z, d); o.w = __fdiv_rn(v.w, d);
        ((float4*)Y)[i] = o;
        __half2 h0 = __float22half2_rn(make_float2(o.x, o.y));
        __half2 h1 = __float22half2_rn(make_float2(o.z, o.w));
        uint2 pk;
        pk.x = *reinterpret_cast<unsigned*>(&h0);
        pk.y = *reinterpret_cast<unsigned*>(&h1);
        ((uint2*)Yh)[i] = pk;
    }
}

// ---------------- group batches by selected action ----------------
__global__ void group_kernel(const int* __restrict__ actions) {
    __shared__ int cnt[Az], cur[Az];
    int tid = threadIdx.x;
    for (int t = 0; t < NSTEP; t++) {
        if (tid < Az) cnt[tid] = 0;
        __syncthreads();
        for (int b = tid; b < Bsz; b += blockDim.x)
            atomicAdd(&cnt[actions[b * NSTEP + t]], 1);
        __syncthreads();
        if (tid == 0) {
            int off = 0;
            for (int a = 0; a < Az; a++) {
                cur[a] = off;
                off += ((cnt[a] + 127) >> 7) << 7;
            }
        }
        __syncthreads();
        for (int i = tid; i < MT * 128; i += blockDim.x) g_row_map[t][i] = -1;
        __syncthreads();
        for (int b = tid; b < Bsz; b += blockDim.x) {
            int a = actions[b * NSTEP + t];
            int p = atomicAdd(&cur[a], 1);
            g_row_map[t][p] = b;
        }
        if (tid < MT) {
            int mt = tid, act = -1, off = 0;
            for (int a = 0; a < Az; a++) {
                int len = ((cnt[a] + 127) >> 7) << 7;
                if (mt * 128 >= off && mt * 128 < off + len) act = a;
                off += len;
            }
            g_tile_action[t][mt] = act;
        }
        __syncthreads();
    }
}

// ---------------- HMMA fp16 approx GEMM + per-block row maxes ----------------
__global__ __launch_bounds__(256, 2) void sims_mma(int t) {
    extern __shared__ unsigned char dyn_smem[];
    __shared__ int rs[128];
    __shared__ unsigned s_rmax[2][128];

    int mt = blockIdx.y;
    int act = g_tile_action[t][mt];
    if (act < 0) return;
    int n0 = blockIdx.x * 128;

    int tid = threadIdx.x, wid = tid >> 5, lane = tid & 31;
    if (tid < 128) rs[tid] = g_row_map[t][mt * 128 + tid];
    __syncthreads();

    unsigned char* base = (unsigned char*)(((uintptr_t)dyn_smem + 1023) & ~(uintptr_t)1023);
    uint32_t sAu[2] = { smem_u32(base),         smem_u32(base + 16384) };
    uint32_t sBu[2] = { smem_u32(base + 32768), smem_u32(base + 49152) };

    int warp_m = wid >> 1, warp_n = wid & 1;
    int m_base = warp_m * 32, nb_base = warp_n * 64;

    const uint4* qb = (const uint4*)g_qh;
    const uint4* kb = (const uint4*)(g_kh + ((size_t)act * Nz + n0) * Dz);

    float c[2][8][4];
#pragma unroll
    for (int i = 0; i < 2; i++)
#pragma unroll
        for (int j = 0; j < 8; j++)
#pragma unroll
            for (int k = 0; k < 4; k++) c[i][j][k] = 0.f;

    int lrow = lane & 15, lslot = lane >> 4;

    int srow_[4], si4_[4], sar_[4];
    unsigned sw_[4];
#pragma unroll
    for (int rep = 0; rep < 4; rep++) {
        int idx = tid + rep * 256;
        srow_[rep] = idx >> 3;
        si4_[rep] = idx & 7;
        sar_[rep] = rs[srow_[rep]];
        sw_[rep] = SMEM_SWZ(srow_[rep] * 128 + si4_[rep] * 16);
    }

    auto stage = [&](int kc, int buf) {
#pragma unroll
        for (int rep = 0; rep < 4; rep++) {
            int ar = sar_[rep];
            cp_async16(sAu[buf] + sw_[rep],
                       qb + (size_t)(ar < 0 ? 0 : ar) * 64 + kc * 8 + si4_[rep], ar >= 0);
            cp_async16(sBu[buf] + sw_[rep],
                       kb + (size_t)srow_[rep] * 64 + kc * 8 + si4_[rep], true);
        }
        CP_COMMIT();
    };

    stage(0, 0);
#pragma unroll 1
    for (int kc = 0; kc < 8; kc++) {
        int buf = kc & 1;
        if (kc + 1 < 8) { stage(kc + 1, buf ^ 1); CP_WAIT(1); }
        else            { CP_WAIT(0); }
        __syncthreads();
#pragma unroll
        for (int k16 = 0; k16 < 4; k16++) {
            int slot16 = (2 * k16 + lslot) * 16;
            uint32_t a[2][4];
#pragma unroll
            for (int mi = 0; mi < 2; mi++) {
                int row = m_base + mi * 16 + lrow;
                ldmatrix_x4(a[mi], sAu[buf] + row * 128 + (slot16 ^ ((row & 7) << 4)));
            }
            uint32_t bf[4][4];
#pragma unroll
            for (int nb = 0; nb < 4; nb++) {
                int row = nb_base + nb * 16 + lrow;
                ldmatrix_x4(bf[nb], sBu[buf] + row * 128 + (slot16 ^ ((row & 7) << 4)));
            }
#pragma unroll
            for (int mi = 0; mi < 2; mi++)
#pragma unroll
                for (int nj = 0; nj < 8; nj++) {
                    int nb = nj >> 1, hi = nj & 1;
                    mma_16816(c[mi][nj], a[mi], bf[nb][hi], bf[nb][hi + 2]);
                }
        }
        __syncthreads();
    }

    // epilogue: store half sims + per-row block-max keys
    unsigned km[2][2];
    km[0][0] = km[0][1] = km[1][0] = km[1][1] = 0u;
#pragma unroll
    for (int mi = 0; mi < 2; mi++) {
        int r0 = rs[m_base + mi * 16 + (lane >> 2)];
        int r1 = rs[m_base + mi * 16 + (lane >> 2) + 8];
#pragma unroll
        for (int nj = 0; nj < 8; nj++) {
            int col = n0 + nb_base + nj * 8 + (lane & 3) * 2;
            __half2 h0 = __floats2half2_rn(c[mi][nj][0], c[mi][nj][1]);
            __half2 h1 = __floats2half2_rn(c[mi][nj][2], c[mi][nj][3]);
            unsigned u0 = *reinterpret_cast<unsigned*>(&h0);
            unsigned u1 = *reinterpret_cast<unsigned*>(&h1);
            km[mi][0] = max(km[mi][0], max(hsort16(u0 & 0xFFFFu), hsort16(u0 >> 16)));
            km[mi][1] = max(km[mi][1], max(hsort16(u1 & 0xFFFFu), hsort16(u1 >> 16)));
            if (r0 >= 0) *(unsigned*)(g_simh + (size_t)r0 * Nz + col) = u0;
            if (r1 >= 0) *(unsigned*)(g_simh + (size_t)r1 * Nz + col) = u1;
        }
    }
#pragma unroll
    for (int mi = 0; mi < 2; mi++)
#pragma unroll
        for (int rr = 0; rr < 2; rr++) {
            unsigned v = km[mi][rr];
            v = max(v, __shfl_xor_sync(0xffffffffu, v, 1));
            v = max(v, __shfl_xor_sync(0xffffffffu, v, 2));
            if ((lane & 3) == 0)
                s_rmax[warp_n][m_base + mi * 16 + (lane >> 2) + rr * 8] = v;
        }
    __syncthreads();
    if (tid < 128) {
        int r = rs[tid];
        if (r >= 0)
            g_bmaxkey[r * 128 + blockIdx.x] = max(s_rmax[0][tid], s_rmax[1][tid]);
    }
}

// ---------------- topk: block-max threshold -> 1 scan -> a50 refine -> exact rescoring ----------------
__global__ __launch_bounds__(256) void topk_kernel(const float* __restrict__ memv,
                                                   const int* __restrict__ actions, int t) {
    __shared__ unsigned s_bk[128];
    __shared__ unsigned char s_skip[128];
    __shared__ unsigned sh_T0, sh_a50;
    __shared__ float4 s_q4[Dz / 4];
    __shared__ int   s_cidx[CAND_CAP];
    __shared__ float s_cvala[CAND_CAP];   // approx values
    __shared__ float s_cval[CAND_CAP];    // exact values (or -inf)
    __shared__ int   s_cnt;
    __shared__ float s_val[TOPK];
    __shared__ int   s_idx[TOPK];
    __shared__ float s_cur[Dz];
    __shared__ float s_acc8[8];
    __shared__ float sh_denom;

    int b = blockIdx.x;
    int tid = threadIdx.x;
    const uint4* srow8 = (const uint4*)(g_simh + (size_t)b * Nz);

    if (tid == 0) { s_cnt = 0; sh_T0 = 0xFFFFFFFFu; sh_a50 = 0xFFFFFFFFu; }
    if (tid < 128) s_bk[tid] = g_bmaxkey[b * 128 + tid];
    for (int i = tid; i < Dz; i += 256)
        ((float*)s_q4)[i] = g_qn[(size_t)b * Dz + i];
    __syncthreads();

    // 50th-largest block max (M50 <= row's rank-50 value)
    if (tid < 128) {
        unsigned v = s_bk[tid];
        int cg = 0;
        for (int j = 0; j < 128; j++) cg += (s_bk[j] > v);
        if (cg <= 49) atomicMin(&sh_T0, v);
    }
    __syncthreads();
    float Tf = hkey2float(sh_T0) - MARGIN;
    if (tid < 128) s_skip[tid] = (hkey2float(s_bk[tid]) < Tf) ? 1 : 0;
    __syncthreads();

    // single candidate scan with block skipping
    for (int i8 = tid; i8 < Nz / 8; i8 += 256) {
        if (s_skip[i8 >> 4]) continue;
        uint4 v = srow8[i8];
        unsigned w[4] = {v.x, v.y, v.z, v.w};
#pragma unroll
        for (int c2 = 0; c2 < 4; c2++) {
            float2 f = __half22float2(*reinterpret_cast<__half2*>(&w[c2]));
            if (f.x >= Tf) {
                int p = atomicAdd(&s_cnt, 1);
                if (p < CAND_CAP) { s_cidx[p] = i8 * 8 + c2 * 2; s_cvala[p] = f.x; }
            }
            if (f.y >= Tf) {
                int p = atomicAdd(&s_cnt, 1);
                if (p < CAND_CAP) { s_cidx[p] = i8 * 8 + c2 * 2 + 1; s_cvala[p] = f.y; }
            }
        }
    }
    __syncthreads();
    int C = min(s_cnt, CAND_CAP);

    // a50 = 50th-largest approx value among candidates (== global approx rank-50)
    for (int c = tid; c < C; c += 256) {
        float v = s_cvala[c];
        int cg = 0;
        for (int j = 0; j < C; j++) cg += (s_cvala[j] > v);
        if (cg <= 49) {
            unsigned u = __float_as_uint(v);
            u = (u & 0x80000000u) ? ~u : (u | 0x80000000u);
            atomicMin(&sh_a50, u);
        }
    }
    __syncthreads();
    unsigned ua = sh_a50;
    ua = (ua & 0x80000000u) ? (ua ^ 0x80000000u) : ~ua;
    float ft = __uint_as_float(ua) - MARGIN;

    // exact fp32 rescoring of the refined set (d-ascending fmaf chain, frozen numerics)
    int a = actions[b * NSTEP + t];
    const float* knb = g_kn + (size_t)a * Nz * Dz;
    for (int c = tid; c < C; c += 256) {
        if (s_cvala[c] < ft) { s_cval[c] = -3.4e38f; continue; }
        const float4* kr = (const float4*)(knb + (size_t)s_cidx[c] * Dz);
        float acc = 0.f;
#pragma unroll 4
        for (int d4 = 0; d4 < Dz / 4; d4++) {
            float4 kv = __ldg(&kr[d4]);
            float4 qv = s_q4[d4];
            acc = fmaf(qv.x, kv.x, acc);
            acc = fmaf(qv.y, kv.y, acc);
            acc = fmaf(qv.z, kv.z, acc);
            acc = fmaf(qv.w, kv.w, acc);
        }
        s_cval[c] = acc;
    }
    __syncthreads();

    // exact ranking (value desc, index asc) into slots 0..49
    for (int c = tid; c < C; c += 256) {
        float v = s_cval[c];
        int id = s_cidx[c];
        int rank = 0;
        for (int j = 0; j < C; j++) {
            float vj = s_cval[j];
            rank += (vj > v) || (vj == v && s_cidx[j] < id);
        }
        if (rank < TOPK) { s_val[rank] = v; s_idx[rank] = id; }
    }
    __syncthreads();

    if (tid == 0) {
        float mx = s_val[0];
        float sum = 0.f;
        for (int k2 = 0; k2 < TOPK; k2++) {
            float e = ref_exp(s_val[k2] - mx);
            s_val[k2] = e;
            sum += e;
        }
        for (int k2 = 0; k2 < TOPK; k2++) s_val[k2] = __fdiv_rn(s_val[k2], sum);
    }
    __syncthreads();

    const float* vb = memv + (size_t)a * Nz * Dz;
    float a0 = 0.f, a1 = 0.f;
    int d0 = tid, d1 = tid + 256;
    for (int k2 = 0; k2 < TOPK; k2++) {
        const float* vr = vb + (size_t)s_idx[k2] * Dz;
        float w2 = s_val[k2];
        a0 = fmaf(w2, vr[d0], a0);
        a1 = fmaf(w2, vr[d1], a1);
    }
    s_cur[d0] = a0;
    s_cur[d1] = a1;
    g_cur[b * Dz + d0] = a0;
    g_cur[b * Dz + d1] = a1;
    __syncthreads();

    if (tid < 8) {
        float acc = 0.f;
        for (int i = 0; i < Dz / 8; i++) {
            float x = s_cur[8 * i + tid];
            acc = fmaf(x, x, acc);
        }
        s_acc8[tid] = acc;
    }
    __syncthreads();
    if (tid == 0) {
        float e0 = s_acc8[0] + s_acc8[4], e1 = s_acc8[1] + s_acc8[5];
        float e2 = s_acc8[2] + s_acc8[6], e3 = s_acc8[3] + s_acc8[7];
        float f0 = e0 + e2, f1 = e1 + e3;
        sh_denom = __fsqrt_rn(f0 + f1) + 1e-8f;
    }
    __syncthreads();
    float dn = sh_denom;
    float q0 = __fdiv_rn(a0, dn);
    float q1 = __fdiv_rn(a1, dn);
    g_qn[b * Dz + d0] = q0;
    g_qn[b * Dz + d1] = q1;
    g_qh[b * Dz + d0] = __float2half_rn(q0);
    g_qh[b * Dz + d1] = __float2half_rn(q1);
}

// ---------------- fused 3-layer MLP (512->256->128->1, elu) ----------------
__global__ __launch_bounds__(256) void mlp_kernel(const float* __restrict__ emb, int use_emb,
                                                  const float* __restrict__ W1, const float* __restrict__ b1,
                                                  const float* __restrict__ W2, const float* __restrict__ b2,
                                                  const float* __restrict__ W3, const float* __restrict__ b3,
                                                  float* __restrict__ out, int off, int stride) {
    __shared__ float Xs[8 * 512];
    __shared__ float H1[8 * 256];
    __shared__ float H2[8 * 128];
    const float* X = use_emb ? emb : g_cur;
    int tid = threadIdx.x;
    int b0 = blockIdx.x * 8;

    for (int i = tid; i < 8 * 512; i += 256) Xs[i] = X[(size_t)b0 * 512 + i];
    __syncthreads();
    {
        int j = tid;
        float acc[8];
#pragma unroll
        for (int bb = 0; bb < 8; bb++) acc[bb] = 0.f;
        for (int d = 0; d < 512; d += 4) {
            float w0 = W1[(d + 0) * 256 + j];
            float w1 = W1[(d + 1) * 256 + j];
            float w2v = W1[(d + 2) * 256 + j];
            float w3v = W1[(d + 3) * 256 + j];
#pragma unroll
            for (int bb = 0; bb < 8; bb++) {
                float4 x = *(const float4*)(&Xs[bb * 512 + d]);
                acc[bb] = fmaf(x.x, w0, acc[bb]);
                acc[bb] = fmaf(x.y, w1, acc[bb]);
                acc[bb] = fmaf(x.z, w2v, acc[bb]);
                acc[bb] = fmaf(x.w, w3v, acc[bb]);
            }
        }
        float bj = b1[j];
#pragma unroll
        for (int bb = 0; bb < 8; bb++) {
            float h = acc[bb] + bj;
            H1[bb * 256 + j] = (h > 0.f) ? h : expm1f(h);
        }
    }
    __syncthreads();
    {
        int j2 = tid & 127, g = tid >> 7;
        float acc[4] = {0.f, 0.f, 0.f, 0.f};
        for (int j = 0; j < 256; j++) {
            float w = W2[j * 128 + j2];
#pragma unroll
            for (int ii = 0; ii < 4; ii++) acc[ii] = fmaf(H1[(g * 4 + ii) * 256 + j], w, acc[ii]);
        }
        float bj = b2[j2];
#pragma unroll
        for (int ii = 0; ii < 4; ii++) {
            float h = acc[ii] + bj;
            H2[(g * 4 + ii) * 128 + j2] = (h > 0.f) ? h : expm1f(h);
        }
    }
    __syncthreads();
    {
        int wid = tid >> 5, lane = tid & 31;
        float s = 0.f;
        for (int j = lane; j < 128; j += 32) s = fmaf(H2[wid * 128 + j], W3[j], s);
        s = warp_sum(s);
        if (lane == 0) out[off + (size_t)(b0 + wid) * stride] = s + b3[0];
    }
}

// ---------------- orchestration ----------------
extern "C" void kernel_launch(void* const* d_in, const int* in_sizes, int n_in,
                              void* d_out, int out_size) {
    const float* emb     = (const float*)d_in[0];
    const float* keys    = (const float*)d_in[1];
    const float* memv    = (const float*)d_in[2];
    const float* W1      = (const float*)d_in[3];
    const float* b1      = (const float*)d_in[4];
    const float* W2      = (const float*)d_in[5];
    const float* b2      = (const float*)d_in[6];
    const float* W3      = (const float*)d_in[7];
    const float* b3      = (const float*)d_in[8];
    const int*   actions = (const int*)d_in[9];
    float* out = (float*)d_out;

    cudaFuncSetAttribute(sims_mma, cudaFuncAttributeMaxDynamicSharedMemorySize, SIMS_DYN_SMEM);

    row_denom_kernel<<<(Az * Nz + 255) / 256, 256>>>(keys, 0, Az * Nz);
    normalize_kernel<<<2048, 256>>>(keys, 0, (Az * Nz * Dz) / 4);
    row_denom_kernel<<<(Bsz + 255) / 256, 256>>>(emb, 1, Bsz);
    normalize_kernel<<<512, 256>>>(emb, 1, (Bsz * Dz) / 4);
    group_kernel<<<1, 256>>>(actions);

    mlp_kernel<<<Bsz / 8, 256>>>(emb, 1, W1, b1, W2, b2, W3, b3, out, 0, 1);

    for (int t = 0; t < NSTEP; t++) {
        sims_mma<<<dim3(Nz / 128, MT), 256, SIMS_DYN_SMEM>>>(t);
        topk_kernel<<<Bsz, 256>>>(memv, actions, t);
        mlp_kernel<<<Bsz / 8, 256>>>(emb, 0, W1, b1, W2, b2, W3, b3, out, Bsz + t, 5);
    }
}